// round 12
// baseline (speedup 1.0000x reference)
#include <cuda_runtime.h>
#include <cuda_fp16.h>
#include <stdint.h>

// Problem constants
#define BATCH 8
#define LQ    1024
#define LKV   2048
#define HID   1024
#define QDIM  1024

typedef __half f16;

// ================= scratch (static device globals) =================
__device__ __align__(16) f16 g_qc [(size_t)BATCH * LQ  * QDIM];   // query fp16
__device__ __align__(16) f16 g_kvcomp[(size_t)BATCH * LKV * QDIM]; // compacted kv fp16
__device__ __align__(16) f16 g_WqT[(size_t)HID * QDIM];
__device__ __align__(16) f16 g_WkT[(size_t)HID * QDIM];
__device__ __align__(16) f16 g_WvT[(size_t)HID * QDIM];
__device__ __align__(16) f16 g_WoT[(size_t)HID * QDIM];
__device__ __align__(16) f16  g_Qh [(size_t)BATCH * LQ  * HID];
__device__ __align__(16) f16  g_Kh [(size_t)BATCH * LKV * HID];   // compacted K
__device__ __align__(16) f16  g_VT [(size_t)BATCH * HID * LKV];   // compacted V^T
__device__ __align__(16) float g_Sf [(size_t)BATCH * LQ  * LKV];  // compacted scores
__device__ __align__(16) f16  g_Ph [(size_t)BATCH * LQ  * LKV];   // compacted probs
__device__ __align__(16) f16  g_Ch [(size_t)BATCH * LQ  * HID];
__device__ int g_idx[(size_t)BATCH * LKV];   // compaction index
__device__ int g_nvalid[BATCH];
__device__ int g_lkvp[BATCH];                // nvalid rounded up to 128

// ================= host-side streams/events (static init, pre-checkpoint) ===
struct HxStreams {
    cudaStream_t s2;
    cudaEvent_t evFork, evKV, evS0, evS1, evP0, evP1;
    HxStreams() {
        cudaStreamCreateWithFlags(&s2, cudaStreamNonBlocking);
        cudaEventCreateWithFlags(&evFork, cudaEventDisableTiming);
        cudaEventCreateWithFlags(&evKV,   cudaEventDisableTiming);
        cudaEventCreateWithFlags(&evS0,   cudaEventDisableTiming);
        cudaEventCreateWithFlags(&evS1,   cudaEventDisableTiming);
        cudaEventCreateWithFlags(&evP0,   cudaEventDisableTiming);
        cudaEventCreateWithFlags(&evP1,   cudaEventDisableTiming);
    }
};
static HxStreams g_hx;

// ================= PTX helpers =================
__device__ __forceinline__ uint32_t smem_to_u32(const void* p) {
    uint32_t a;
    asm("{ .reg .u64 t; cvta.to.shared.u64 t, %1; cvt.u32.u64 %0, t; }"
        : "=r"(a) : "l"(p));
    return a;
}

#define SWZ128(o) ((o) ^ (((o) >> 3) & 0x70))

__device__ __forceinline__ void cp16(uint32_t saddr, const void* g) {
    asm volatile("cp.async.cg.shared.global [%0], [%1], 16;"
                 :: "r"(saddr), "l"(g) : "memory");
}
#define CP_COMMIT() asm volatile("cp.async.commit_group;" ::: "memory")
#define CP_WAIT1()  asm volatile("cp.async.wait_group 1;" ::: "memory")
#define CP_WAIT0()  asm volatile("cp.async.wait_group 0;" ::: "memory")

__device__ __forceinline__ void ldsm4(uint32_t* r, uint32_t addr) {
    asm volatile("ldmatrix.sync.aligned.m8n8.x4.shared.b16 {%0,%1,%2,%3}, [%4];"
                 : "=r"(r[0]), "=r"(r[1]), "=r"(r[2]), "=r"(r[3]) : "r"(addr));
}

__device__ __forceinline__ void mma16816(float* d, const uint32_t* a,
                                         uint32_t b0, uint32_t b1) {
    asm volatile(
        "mma.sync.aligned.m16n8k16.row.col.f32.f16.f16.f32 "
        "{%0,%1,%2,%3}, {%4,%5,%6,%7}, {%8,%9}, {%0,%1,%2,%3};"
        : "+f"(d[0]), "+f"(d[1]), "+f"(d[2]), "+f"(d[3])
        : "r"(a[0]), "r"(a[1]), "r"(a[2]), "r"(a[3]), "r"(b0), "r"(b1));
}

// ================= compaction (self-detecting mask dtype) =================
// One block per batch: detect u8-vs-i32 layout, then block-scan over 2048
// mask values -> g_idx/g_nvalid/g_lkvp.
__global__ void __launch_bounds__(256)
build_compact_kernel(const void* __restrict__ mask_raw)
{
    const int b   = blockIdx.x;
    const int tid = threadIdx.x;

    // --- dtype detect: scan first 4096 int words (16KB; L2-hot) ---
    __shared__ int s_bad;
    if (tid == 0) s_bad = 0;
    __syncthreads();
    {
        const int* w = (const int*)mask_raw;
        int bad = 0;
        for (int i = tid; i < 4096; i += 256)
            if ((unsigned)w[i] > 1u) bad = 1;
        if (bad) atomicOr(&s_bad, 1);
    }
    __syncthreads();
    const int is_u8 = s_bad;

    const int base = tid * 8;
    int m[8], cnt = 0;
    #pragma unroll
    for (int i = 0; i < 8; i++) {
        const int gi = b * LKV + base + i;
        int v = is_u8 ? (((const uint8_t*)mask_raw)[gi] != 0)
                      : (((const int*)mask_raw)[gi] != 0);
        m[i] = v;
        cnt += v;
    }

    const int lane = tid & 31, w = tid >> 5;
    int v = cnt;
    #pragma unroll
    for (int o = 1; o < 32; o <<= 1) {
        int t = __shfl_up_sync(0xFFFFFFFFu, v, o);
        if (lane >= o) v += t;
    }
    __shared__ int ws[8];
    if (lane == 31) ws[w] = v;
    __syncthreads();
    __shared__ int total;
    if (tid == 0) {
        int s = 0;
        #pragma unroll
        for (int i = 0; i < 8; i++) { int t = ws[i]; ws[i] = s; s += t; }
        total = s;
    }
    __syncthreads();
    int pos = v - cnt + ws[w];

    #pragma unroll
    for (int i = 0; i < 8; i++)
        if (m[i]) g_idx[b * LKV + pos++] = base + i;

    if (tid == 0) {
        g_nvalid[b] = total;
        g_lkvp[b]   = (total + 127) & ~127;
    }
}

// Gather + fp32->fp16 convert: kvcomp[b][j] = kv[b][idx[b][j]] ; pad rows = 0.
__global__ void __launch_bounds__(128)
gather_kv_kernel(const float* __restrict__ kv)
{
    const int j = blockIdx.x, b = blockIdx.y, t = threadIdx.x;
    if (j >= g_lkvp[b]) return;
    f16* dst = g_kvcomp + ((size_t)b * LKV + j) * QDIM;
    if (j < g_nvalid[b]) {
        const float* src = kv + ((size_t)b * LKV + g_idx[b * LKV + j]) * QDIM;
        float4 a = *(const float4*)(src + t * 8);
        float4 c = *(const float4*)(src + t * 8 + 4);
        f16 h[8] = {__float2half_rn(a.x), __float2half_rn(a.y),
                    __float2half_rn(a.z), __float2half_rn(a.w),
                    __float2half_rn(c.x), __float2half_rn(c.y),
                    __float2half_rn(c.z), __float2half_rn(c.w)};
        *(uint4*)(dst + t * 8) = *(uint4*)h;
    } else {
        *(uint4*)(dst + t * 8) = make_uint4(0, 0, 0, 0);
    }
}

// ================= elementwise fp32 -> fp16 convert =================
__global__ void __launch_bounds__(256)
convert_kernel(const float* __restrict__ x, f16* __restrict__ h, long long n4)
{
    long long i = blockIdx.x * 256 + threadIdx.x;
    if (i >= n4) return;
    float4 v = *(const float4*)(x + i * 4);
    f16 hh[4] = {__float2half_rn(v.x), __float2half_rn(v.y),
                 __float2half_rn(v.z), __float2half_rn(v.w)};
    *(uint2*)(h + i * 4) = *(uint2*)hh;
}

// ======= batched 1024x1024 transpose: W[z][R][C] fp32 -> WT[z][C][R] fp16 =======
struct WTArgs {
    const float* src[4];
    f16*         dst[4];
};

__global__ void __launch_bounds__(256)
wtrans_kernel(WTArgs args)
{
    __shared__ float t[32][33];
    const float* x = args.src[blockIdx.z];
    f16*        th = args.dst[blockIdx.z];
    const int bc = blockIdx.x * 32;
    const int br = blockIdx.y * 32;
    const int tx = threadIdx.x, ty = threadIdx.y;
    #pragma unroll
    for (int j = 0; j < 32; j += 8)
        t[ty + j][tx] = x[(long long)(br + ty + j) * 1024 + bc + tx];
    __syncthreads();
    #pragma unroll
    for (int j = 0; j < 32; j += 8)
        th[(long long)(bc + ty + j) * 1024 + br + tx] = __float2half_rn(t[tx][ty + j]);
}

// ================= persistent single-pass fp16 HMMA GEMM =================
// C[M,N] = A[M,K] @ B[N,K]^T, fp32 accumulate.
// CTA 128x128 tile, K-tile 64, 8 warps (4M x 2N), 3-stage cp.async pipeline.
// Persistent: 1-D grid strides over linearized (gz, gy, gx) tile space.
// EPI: 0=+bias[col]->f16 ; 1=+bias[col]->fp32 ; 2=compact mask*scale->fp32 ;
//      3=plain->f16 ; 5=+bias[row]->f16 (transposed projection)
// VAR: 0=none ; 1=M limited by lkvp[b] ; 2=N limited (EPI2 masks by nvalid) ;
//      3=K runtime = lkvp[b]
#define BKT 64
#define STAGE_B 32768
#define NSTAGE 3
#define DSMEM_B (NSTAGE * STAGE_B)   // 96KB

template <int EPI, int VAR>
__global__ void __launch_bounds__(256, 2)
mma_gemm(const f16* __restrict__ A, const f16* __restrict__ B,
         float* __restrict__ Cf, f16* __restrict__ Oh,
         const float* __restrict__ bias,
         const int* __restrict__ d_nv, const int* __restrict__ d_lkvp,
         float scale, int N, int KdHost, int ldA, int ldB,
         long long sA, long long sB, long long sC,
         int gx, int gy, int gz)
{
    extern __shared__ char smem[];
    const uint32_t sbase = smem_to_u32(smem);

    const int tid  = threadIdx.x;
    const int wid = tid >> 5, lane = tid & 31;
    const int wm = wid & 3;
    const int wn = wid >> 2;
    const int ntiles = gx * gy * gz;

    for (int t = blockIdx.x; t < ntiles; t += gridDim.x) {
        const int b  = t / (gx * gy);
        const int r2 = t - b * (gx * gy);
        const int ty = r2 / gx;
        const int tx = r2 - ty * gx;
        const int tileM = ty * 128;
        const int tileN = tx * 128;

        int lim = 0;
        if (VAR != 0) lim = d_lkvp[b];
        if (VAR == 1 && tileM >= lim) continue;
        if (VAR == 2 && tileN >= lim) continue;
        const int Kd = (VAR == 3) ? lim : KdHost;

        const f16* baseA = A + (long long)b * sA + (long long)tileM * ldA;
        const f16* baseB = B + (long long)b * sB + (long long)tileN * ldB;

        float acc[2][8][4];
        #pragma unroll
        for (int mi = 0; mi < 2; mi++)
            #pragma unroll
            for (int nj = 0; nj < 8; nj++)
                #pragma unroll
                for (int q = 0; q < 4; q++) acc[mi][nj][q] = 0.0f;

        const int KT = Kd / BKT;

        auto load_stage = [&](int kt, int s) {
            const int k0 = kt * BKT;
            #pragma unroll
            for (int sub = 0; sub < 2; sub++) {
                const f16* gb = sub ? baseB : baseA;
                const int ld  = sub ? ldB : ldA;
                const uint32_t so = sbase + s * STAGE_B + sub * 16384;
                #pragma unroll
                for (int i = 0; i < 4; i++) {
                    const int c  = i * 256 + tid;
                    const int r  = c >> 3;
                    const int kc = c & 7;
                    cp16(so + SWZ128((uint32_t)(r * 128 + kc * 16)),
                         gb + (long long)r * ld + k0 + kc * 8);
                }
            }
            CP_COMMIT();
        };

        load_stage(0, 0);
        if (KT > 1) load_stage(1, 1);

        for (int kt = 0; kt < KT; kt++) {
            const int s = kt % NSTAGE;
            if (kt + 1 < KT) CP_WAIT1(); else CP_WAIT0();
            __syncthreads();
            if (kt + 2 < KT) load_stage(kt + 2, (kt + 2) % NSTAGE);

            const uint32_t aS = sbase + s * STAGE_B;
            const uint32_t bS = aS + 16384;

            #pragma unroll
            for (int ks = 0; ks < 4; ks++) {
                const int chunk = ks * 32 + (lane >> 4) * 16;
                uint32_t af[2][4];
                #pragma unroll
                for (int mi = 0; mi < 2; mi++) {
                    const int r = wm * 32 + mi * 16 + (lane & 15);
                    ldsm4(af[mi], aS + SWZ128((uint32_t)(r * 128 + chunk)));
                }
                uint32_t bf[4][4];
                #pragma unroll
                for (int ni = 0; ni < 4; ni++) {
                    const int r = wn * 64 + ni * 16 + (lane & 15);
                    ldsm4(bf[ni], bS + SWZ128((uint32_t)(r * 128 + chunk)));
                }
                #pragma unroll
                for (int mi = 0; mi < 2; mi++) {
                    #pragma unroll
                    for (int nj = 0; nj < 8; nj++) {
                        const int ni = nj >> 1, oct = nj & 1;
                        mma16816(acc[mi][nj], af[mi], bf[ni][oct], bf[ni][oct + 2]);
                    }
                }
            }
        }

        // ---- epilogue ----
        float* cf = Cf ? Cf + (long long)b * sC : nullptr;
        f16*   oh = Oh ? Oh + (long long)b * sC : nullptr;
        const int nv = (VAR == 2 && EPI == 2) ? d_nv[b] : 0;

        #pragma unroll
        for (int mi = 0; mi < 2; mi++) {
            #pragma unroll
            for (int nj = 0; nj < 8; nj++) {
                const int row = tileM + wm * 32 + mi * 16 + (lane >> 2);
                const int col = tileN + wn * 64 + nj * 8 + (lane & 3) * 2;
                #pragma unroll
                for (int half = 0; half < 2; half++) {
                    const int r = row + half * 8;
                    float v0 = acc[mi][nj][half * 2];
                    float v1 = acc[mi][nj][half * 2 + 1];
                    if (EPI == 0 || EPI == 1) {
                        v0 += __ldg(bias + col);
                        v1 += __ldg(bias + col + 1);
                    } else if (EPI == 2) {
                        v0 = (col     < nv) ? v0 * scale : -1e9f;
                        v1 = (col + 1 < nv) ? v1 * scale : -1e9f;
                    } else if (EPI == 5) {
                        const float bv = __ldg(bias + r);
                        v0 += bv;
                        v1 += bv;
                    }
                    if (EPI == 1 || EPI == 2) {
                        *(float2*)(cf + (long long)r * N + col) = make_float2(v0, v1);
                    } else {
                        f16 h2[2] = {__float2half_rn(v0), __float2half_rn(v1)};
                        *(uint32_t*)(oh + (long long)r * N + col) = *(uint32_t*)h2;
                    }
                }
            }
        }
        __syncthreads();   // all warps done with epilogue before next tile reuses smem
    }
}

// ============ softmax over compacted row length lkvp[b] ============
// Pointers may be pre-offset to a batch chunk; d_lkvp is offset to match.
__global__ void __launch_bounds__(256)
softmax_kernel(const float* __restrict__ S, f16* __restrict__ Ph,
               const int* __restrict__ d_lkvp)
{
    const int b = blockIdx.x >> 10;          // LQ = 1024 rows per batch
    const int len = d_lkvp[b];
    const long long ro = (long long)blockIdx.x * LKV;
    const int tid = threadIdx.x;
    const bool active = (tid * 8) < len;

    float vals[8];
    if (active) {
        const float* row = S + ro + tid * 8;
        *(float4*)(vals)     = *(const float4*)(row);
        *(float4*)(vals + 4) = *(const float4*)(row + 4);
    } else {
        #pragma unroll
        for (int i = 0; i < 8; i++) vals[i] = -1e30f;
    }

    float mx = vals[0];
    #pragma unroll
    for (int i = 1; i < 8; i++) mx = fmaxf(mx, vals[i]);

    __shared__ float red[8];
    #pragma unroll
    for (int o = 16; o > 0; o >>= 1)
        mx = fmaxf(mx, __shfl_xor_sync(0xFFFFFFFFu, mx, o));
    if ((tid & 31) == 0) red[tid >> 5] = mx;
    __syncthreads();
    if (tid == 0) {
        float v = red[0];
        #pragma unroll
        for (int w = 1; w < 8; w++) v = fmaxf(v, red[w]);
        red[0] = v;
    }
    __syncthreads();
    mx = red[0];

    float sum = 0.0f;
    #pragma unroll
    for (int i = 0; i < 8; i++) {
        vals[i] = __expf(vals[i] - mx);
        sum += vals[i];
    }
    __syncthreads();
    #pragma unroll
    for (int o = 16; o > 0; o >>= 1)
        sum += __shfl_xor_sync(0xFFFFFFFFu, sum, o);
    if ((tid & 31) == 0) red[tid >> 5] = sum;
    __syncthreads();
    if (tid == 0) {
        float v = red[0];
        #pragma unroll
        for (int w = 1; w < 8; w++) v += red[w];
        red[0] = v;
    }
    __syncthreads();
    const float inv = 1.0f / red[0];

    if (active) {
        f16 h[8];
        #pragma unroll
        for (int i = 0; i < 8; i++) h[i] = __float2half_rn(vals[i] * inv);
        *(uint4*)(Ph + ro + tid * 8) = *(uint4*)h;
    }
}

// ================= host launcher =================
extern "C" void kernel_launch(void* const* d_in, const int* in_sizes, int n_in,
                              void* d_out, int out_size)
{
    const float* query = (const float*)d_in[0];
    const float* kv    = (const float*)d_in[1];
    const void*  mask  = d_in[2];
    const float* Wq = (const float*)d_in[3];
    const float* bq = (const float*)d_in[4];
    const float* Wk = (const float*)d_in[5];
    const float* bk = (const float*)d_in[6];
    const float* Wv = (const float*)d_in[7];
    const float* bv = (const float*)d_in[8];
    const float* Wo = (const float*)d_in[9];
    const float* bo = (const float*)d_in[10];
    float* out = (float*)d_out;

    f16 *qc, *kvcomp, *WqT, *WkT, *WvT, *WoT;
    f16 *Qh, *Kh, *VT, *Ph, *Ch;
    float *Sf;
    int *NV, *LK;
    cudaGetSymbolAddress((void**)&qc,  g_qc);
    cudaGetSymbolAddress((void**)&kvcomp, g_kvcomp);
    cudaGetSymbolAddress((void**)&WqT, g_WqT);  cudaGetSymbolAddress((void**)&WkT, g_WkT);
    cudaGetSymbolAddress((void**)&WvT, g_WvT);  cudaGetSymbolAddress((void**)&WoT, g_WoT);
    cudaGetSymbolAddress((void**)&Qh, g_Qh);    cudaGetSymbolAddress((void**)&Kh, g_Kh);
    cudaGetSymbolAddress((void**)&VT, g_VT);
    cudaGetSymbolAddress((void**)&Sf, g_Sf);    cudaGetSymbolAddress((void**)&Ph, g_Ph);
    cudaGetSymbolAddress((void**)&Ch, g_Ch);
    cudaGetSymbolAddress((void**)&NV, g_nvalid);
    cudaGetSymbolAddress((void**)&LK, g_lkvp);

    cudaFuncSetAttribute(mma_gemm<0,0>, cudaFuncAttributeMaxDynamicSharedMemorySize, DSMEM_B);
    cudaFuncSetAttribute(mma_gemm<0,1>, cudaFuncAttributeMaxDynamicSharedMemorySize, DSMEM_B);
    cudaFuncSetAttribute(mma_gemm<1,0>, cudaFuncAttributeMaxDynamicSharedMemorySize, DSMEM_B);
    cudaFuncSetAttribute(mma_gemm<2,2>, cudaFuncAttributeMaxDynamicSharedMemorySize, DSMEM_B);
    cudaFuncSetAttribute(mma_gemm<3,3>, cudaFuncAttributeMaxDynamicSharedMemorySize, DSMEM_B);
    cudaFuncSetAttribute(mma_gemm<5,2>, cudaFuncAttributeMaxDynamicSharedMemorySize, DSMEM_B);

    int nsm = 148;
    cudaDeviceGetAttribute(&nsm, cudaDevAttrMultiProcessorCount, 0);
    const int PGRID = nsm * 2;   // one balanced persistent wave (2 CTAs/SM)

    const float scale = 1.0f / 32.0f;  // 1/sqrt(1024)
    cudaStream_t S2 = g_hx.s2;

    // ---- fork: compaction track on S2 (independent of main until K-proj) ----
    cudaEventRecord(g_hx.evFork, 0);
    cudaStreamWaitEvent(S2, g_hx.evFork, 0);
    build_compact_kernel<<<BATCH, 256, 0, S2>>>(mask);
    gather_kv_kernel<<<dim3(LKV, BATCH), 128, 0, S2>>>(kv);
    cudaEventRecord(g_hx.evKV, S2);

    // ---- main: query convert + weight transposes + Q projection ----
    convert_kernel<<<(int)(((long long)BATCH * LQ * QDIM / 4 + 255) / 256), 256>>>(
        query, qc, (long long)BATCH * LQ * QDIM / 4);
    {
        WTArgs wa;
        wa.src[0] = Wq;  wa.dst[0] = WqT;
        wa.src[1] = Wk;  wa.dst[1] = WkT;
        wa.src[2] = Wv;  wa.dst[2] = WvT;
        wa.src[3] = Wo;  wa.dst[3] = WoT;
        wtrans_kernel<<<dim3(32, 32, 4), dim3(32, 8)>>>(wa);
    }
    mma_gemm<0,0><<<PGRID, 256, DSMEM_B>>>(
        qc, WqT, nullptr, Qh, bq, nullptr, nullptr, 0.0f,
        HID, QDIM, QDIM, QDIM, 0, 0, 0,
        HID / 128, (BATCH * LQ) / 128, 1);

    // ---- join: need compacted kv before K/V projections ----
    cudaStreamWaitEvent(0, g_hx.evKV, 0);

    // K projection on compacted rows -> Kh (M limited by lkvp)
    mma_gemm<0,1><<<PGRID, 256, DSMEM_B>>>(
        kvcomp, WkT, nullptr, Kh, bk, NV, LK, 0.0f,
        HID, QDIM, QDIM, QDIM,
        (long long)LKV * QDIM, 0, (long long)LKV * HID,
        HID / 128, LKV / 128, BATCH);

    // V projection directly transposed: VT[b][h][j] (N limited, row bias)
    mma_gemm<5,2><<<PGRID, 256, DSMEM_B>>>(
        WvT, kvcomp, nullptr, VT, bv, NV, LK, 0.0f,
        LKV, QDIM, QDIM, QDIM,
        0, (long long)LKV * QDIM, (long long)HID * LKV,
        LKV / 128, HID / 128, BATCH);

    // ---- chunked scores/softmax/context pipeline (2 chunks of 4 batches) ----
    const int HB = BATCH / 2;  // 4
    const long long offQ = (long long)HB * LQ * HID;
    const long long offK = (long long)HB * LKV * HID;
    const long long offS = (long long)HB * LQ * LKV;
    const long long offV = (long long)HB * HID * LKV;
    const long long offC = (long long)HB * LQ * HID;

    // scores chunk 0
    mma_gemm<2,2><<<PGRID, 256, DSMEM_B>>>(
        Qh, Kh, Sf, nullptr, nullptr, NV, LK, scale,
        LKV, HID, HID, HID,
        (long long)LQ * HID, (long long)LKV * HID, (long long)LQ * LKV,
        LKV / 128, LQ / 128, HB);
    cudaEventRecord(g_hx.evS0, 0);

    // softmax chunk 0 on S2 (overlaps scores chunk 1)
    cudaStreamWaitEvent(S2, g_hx.evS0, 0);
    softmax_kernel<<<HB * LQ, 256, 0, S2>>>(Sf, Ph, LK);
    cudaEventRecord(g_hx.evP0, S2);

    // scores chunk 1
    mma_gemm<2,2><<<PGRID, 256, DSMEM_B>>>(
        Qh + offQ, Kh + offK, Sf + offS, nullptr, nullptr, NV + HB, LK + HB, scale,
        LKV, HID, HID, HID,
        (long long)LQ * HID, (long long)LKV * HID, (long long)LQ * LKV,
        LKV / 128, LQ / 128, HB);
    cudaEventRecord(g_hx.evS1, 0);

    // softmax chunk 1 on S2 (overlaps context chunk 0)
    cudaStreamWaitEvent(S2, g_hx.evS1, 0);
    softmax_kernel<<<HB * LQ, 256, 0, S2>>>(Sf + offS, Ph + offS, LK + HB);
    cudaEventRecord(g_hx.evP1, S2);

    // context chunk 0
    cudaStreamWaitEvent(0, g_hx.evP0, 0);
    mma_gemm<3,3><<<PGRID, 256, DSMEM_B>>>(
        Ph, VT, nullptr, Ch, nullptr, NV, LK, 0.0f,
        HID, 0, LKV, LKV,
        (long long)LQ * LKV, (long long)HID * LKV, (long long)LQ * HID,
        HID / 128, LQ / 128, HB);

    // context chunk 1
    cudaStreamWaitEvent(0, g_hx.evP1, 0);
    mma_gemm<3,3><<<PGRID, 256, DSMEM_B>>>(
        Ph + offS, VT + offV, nullptr, Ch + offC, nullptr, NV + HB, LK + HB, 0.0f,
        HID, 0, LKV, LKV,
        (long long)LQ * LKV, (long long)HID * LKV, (long long)LQ * HID,
        HID / 128, LQ / 128, HB);

    // output projection: out = C @ WoT^T + bo (fp32)
    mma_gemm<1,0><<<PGRID, 256, DSMEM_B>>>(
        Ch, WoT, out, nullptr, bo, nullptr, nullptr, 0.0f,
        QDIM, HID, HID, HID, 0, 0, 0,
        QDIM / 128, (BATCH * LQ) / 128, 1);
}

// round 13
// speedup vs baseline: 1.0284x; 1.0284x over previous
#include <cuda_runtime.h>
#include <cuda_fp16.h>
#include <stdint.h>

// Problem constants
#define BATCH 8
#define LQ    1024
#define LKV   2048
#define HID   1024
#define QDIM  1024

typedef __half f16;

// ================= scratch (static device globals) =================
__device__ __align__(16) f16 g_qc [(size_t)BATCH * LQ  * QDIM];   // query fp16
__device__ __align__(16) f16 g_kvcomp[(size_t)BATCH * LKV * QDIM]; // compacted kv fp16
__device__ __align__(16) f16 g_WqT[(size_t)HID * QDIM];
__device__ __align__(16) f16 g_WkT[(size_t)HID * QDIM];
__device__ __align__(16) f16 g_WvT[(size_t)HID * QDIM];
__device__ __align__(16) f16 g_WoT[(size_t)HID * QDIM];
__device__ __align__(16) f16  g_Qh [(size_t)BATCH * LQ  * HID];
__device__ __align__(16) f16  g_Kh [(size_t)BATCH * LKV * HID];   // compacted K
__device__ __align__(16) f16  g_VT [(size_t)BATCH * HID * LKV];   // compacted V^T
__device__ __align__(16) f16  g_Sh [(size_t)BATCH * LQ  * LKV];   // compacted scores (fp16)
__device__ __align__(16) f16  g_Ph [(size_t)BATCH * LQ  * LKV];   // compacted probs
__device__ __align__(16) f16  g_Ch [(size_t)BATCH * LQ  * HID];
__device__ int g_idx[(size_t)BATCH * LKV];   // compaction index
__device__ int g_nvalid[BATCH];
__device__ int g_lkvp[BATCH];                // nvalid rounded up to 128

// ================= PTX helpers =================
__device__ __forceinline__ uint32_t smem_to_u32(const void* p) {
    uint32_t a;
    asm("{ .reg .u64 t; cvta.to.shared.u64 t, %1; cvt.u32.u64 %0, t; }"
        : "=r"(a) : "l"(p));
    return a;
}

#define SWZ128(o) ((o) ^ (((o) >> 3) & 0x70))

__device__ __forceinline__ void cp16(uint32_t saddr, const void* g) {
    asm volatile("cp.async.cg.shared.global [%0], [%1], 16;"
                 :: "r"(saddr), "l"(g) : "memory");
}
#define CP_COMMIT() asm volatile("cp.async.commit_group;" ::: "memory")
#define CP_WAIT1()  asm volatile("cp.async.wait_group 1;" ::: "memory")
#define CP_WAIT0()  asm volatile("cp.async.wait_group 0;" ::: "memory")

__device__ __forceinline__ void ldsm4(uint32_t* r, uint32_t addr) {
    asm volatile("ldmatrix.sync.aligned.m8n8.x4.shared.b16 {%0,%1,%2,%3}, [%4];"
                 : "=r"(r[0]), "=r"(r[1]), "=r"(r[2]), "=r"(r[3]) : "r"(addr));
}

__device__ __forceinline__ void mma16816(float* d, const uint32_t* a,
                                         uint32_t b0, uint32_t b1) {
    asm volatile(
        "mma.sync.aligned.m16n8k16.row.col.f32.f16.f16.f32 "
        "{%0,%1,%2,%3}, {%4,%5,%6,%7}, {%8,%9}, {%0,%1,%2,%3};"
        : "+f"(d[0]), "+f"(d[1]), "+f"(d[2]), "+f"(d[3])
        : "r"(a[0]), "r"(a[1]), "r"(a[2]), "r"(a[3]), "r"(b0), "r"(b1));
}

// ================= compaction (self-detecting mask dtype) =================
__global__ void __launch_bounds__(256)
build_compact_kernel(const void* __restrict__ mask_raw)
{
    const int b   = blockIdx.x;
    const int tid = threadIdx.x;

    // dtype detect: scan first 4096 int words (16KB; L2-hot)
    __shared__ int s_bad;
    if (tid == 0) s_bad = 0;
    __syncthreads();
    {
        const int* w = (const int*)mask_raw;
        int bad = 0;
        for (int i = tid; i < 4096; i += 256)
            if ((unsigned)w[i] > 1u) bad = 1;
        if (bad) atomicOr(&s_bad, 1);
    }
    __syncthreads();
    const int is_u8 = s_bad;

    const int base = tid * 8;
    int m[8], cnt = 0;
    #pragma unroll
    for (int i = 0; i < 8; i++) {
        const int gi = b * LKV + base + i;
        int v = is_u8 ? (((const uint8_t*)mask_raw)[gi] != 0)
                      : (((const int*)mask_raw)[gi] != 0);
        m[i] = v;
        cnt += v;
    }

    const int lane = tid & 31, w = tid >> 5;
    int v = cnt;
    #pragma unroll
    for (int o = 1; o < 32; o <<= 1) {
        int t = __shfl_up_sync(0xFFFFFFFFu, v, o);
        if (lane >= o) v += t;
    }
    __shared__ int ws[8];
    if (lane == 31) ws[w] = v;
    __syncthreads();
    __shared__ int total;
    if (tid == 0) {
        int s = 0;
        #pragma unroll
        for (int i = 0; i < 8; i++) { int t = ws[i]; ws[i] = s; s += t; }
        total = s;
    }
    __syncthreads();
    int pos = v - cnt + ws[w];

    #pragma unroll
    for (int i = 0; i < 8; i++)
        if (m[i]) g_idx[b * LKV + pos++] = base + i;

    if (tid == 0) {
        g_nvalid[b] = total;
        g_lkvp[b]   = (total + 127) & ~127;
    }
}

// Gather + fp32->fp16 convert: kvcomp[b][j] = kv[b][idx[b][j]] ; pad rows = 0.
__global__ void __launch_bounds__(128)
gather_kv_kernel(const float* __restrict__ kv)
{
    const int j = blockIdx.x, b = blockIdx.y, t = threadIdx.x;
    if (j >= g_lkvp[b]) return;
    f16* dst = g_kvcomp + ((size_t)b * LKV + j) * QDIM;
    if (j < g_nvalid[b]) {
        const float* src = kv + ((size_t)b * LKV + g_idx[b * LKV + j]) * QDIM;
        float4 a = *(const float4*)(src + t * 8);
        float4 c = *(const float4*)(src + t * 8 + 4);
        f16 h[8] = {__float2half_rn(a.x), __float2half_rn(a.y),
                    __float2half_rn(a.z), __float2half_rn(a.w),
                    __float2half_rn(c.x), __float2half_rn(c.y),
                    __float2half_rn(c.z), __float2half_rn(c.w)};
        *(uint4*)(dst + t * 8) = *(uint4*)h;
    } else {
        *(uint4*)(dst + t * 8) = make_uint4(0, 0, 0, 0);
    }
}

// ================= elementwise fp32 -> fp16 convert =================
__global__ void __launch_bounds__(256)
convert_kernel(const float* __restrict__ x, f16* __restrict__ h, long long n4)
{
    long long i = blockIdx.x * 256 + threadIdx.x;
    if (i >= n4) return;
    float4 v = *(const float4*)(x + i * 4);
    f16 hh[4] = {__float2half_rn(v.x), __float2half_rn(v.y),
                 __float2half_rn(v.z), __float2half_rn(v.w)};
    *(uint2*)(h + i * 4) = *(uint2*)hh;
}

// ======= batched 1024x1024 transpose: W[z][R][C] fp32 -> WT[z][C][R] fp16 =======
struct WTArgs {
    const float* src[4];
    f16*         dst[4];
};

__global__ void __launch_bounds__(256)
wtrans_kernel(WTArgs args)
{
    __shared__ float t[32][33];
    const float* x = args.src[blockIdx.z];
    f16*        th = args.dst[blockIdx.z];
    const int bc = blockIdx.x * 32;
    const int br = blockIdx.y * 32;
    const int tx = threadIdx.x, ty = threadIdx.y;
    #pragma unroll
    for (int j = 0; j < 32; j += 8)
        t[ty + j][tx] = x[(long long)(br + ty + j) * 1024 + bc + tx];
    __syncthreads();
    #pragma unroll
    for (int j = 0; j < 32; j += 8)
        th[(long long)(bc + ty + j) * 1024 + br + tx] = __float2half_rn(t[tx][ty + j]);
}

// ================= persistent single-pass fp16 HMMA GEMM =================
// C[M,N] = A[M,K] @ B[N,K]^T, fp32 accumulate.
// CTA 128x128 tile, K-tile 64, 8 warps (4M x 2N), 3-stage cp.async pipeline.
// Persistent: 1-D grid strides over linearized (gz, gy, gx) tile space.
// EPI: 0=+bias[col]->f16 ; 1=+bias[col]->fp32 ; 2=compact mask*scale->f16 ;
//      3=plain->f16 ; 5=+bias[row]->f16 (transposed projection)
// VAR: 0=none ; 1=M limited by lkvp[b] ; 2=N limited (EPI2 masks by nvalid) ;
//      3=K runtime = lkvp[b]
#define BKT 64
#define STAGE_B 32768
#define NSTAGE 3
#define DSMEM_B (NSTAGE * STAGE_B)   // 96KB

template <int EPI, int VAR>
__global__ void __launch_bounds__(256, 2)
mma_gemm(const f16* __restrict__ A, const f16* __restrict__ B,
         float* __restrict__ Cf, f16* __restrict__ Oh,
         const float* __restrict__ bias,
         const int* __restrict__ d_nv, const int* __restrict__ d_lkvp,
         float scale, int N, int KdHost, int ldA, int ldB,
         long long sA, long long sB, long long sC,
         int gx, int gy, int gz)
{
    extern __shared__ char smem[];
    const uint32_t sbase = smem_to_u32(smem);

    const int tid  = threadIdx.x;
    const int wid = tid >> 5, lane = tid & 31;
    const int wm = wid & 3;
    const int wn = wid >> 2;
    const int ntiles = gx * gy * gz;

    for (int t = blockIdx.x; t < ntiles; t += gridDim.x) {
        const int b  = t / (gx * gy);
        const int r2 = t - b * (gx * gy);
        const int ty = r2 / gx;
        const int tx = r2 - ty * gx;
        const int tileM = ty * 128;
        const int tileN = tx * 128;

        int lim = 0;
        if (VAR != 0) lim = d_lkvp[b];
        if (VAR == 1 && tileM >= lim) continue;
        if (VAR == 2 && tileN >= lim) continue;
        const int Kd = (VAR == 3) ? lim : KdHost;

        const f16* baseA = A + (long long)b * sA + (long long)tileM * ldA;
        const f16* baseB = B + (long long)b * sB + (long long)tileN * ldB;

        float acc[2][8][4];
        #pragma unroll
        for (int mi = 0; mi < 2; mi++)
            #pragma unroll
            for (int nj = 0; nj < 8; nj++)
                #pragma unroll
                for (int q = 0; q < 4; q++) acc[mi][nj][q] = 0.0f;

        const int KT = Kd / BKT;

        auto load_stage = [&](int kt, int s) {
            const int k0 = kt * BKT;
            #pragma unroll
            for (int sub = 0; sub < 2; sub++) {
                const f16* gb = sub ? baseB : baseA;
                const int ld  = sub ? ldB : ldA;
                const uint32_t so = sbase + s * STAGE_B + sub * 16384;
                #pragma unroll
                for (int i = 0; i < 4; i++) {
                    const int c  = i * 256 + tid;
                    const int r  = c >> 3;
                    const int kc = c & 7;
                    cp16(so + SWZ128((uint32_t)(r * 128 + kc * 16)),
                         gb + (long long)r * ld + k0 + kc * 8);
                }
            }
            CP_COMMIT();
        };

        load_stage(0, 0);
        if (KT > 1) load_stage(1, 1);

        for (int kt = 0; kt < KT; kt++) {
            const int s = kt % NSTAGE;
            if (kt + 1 < KT) CP_WAIT1(); else CP_WAIT0();
            __syncthreads();
            if (kt + 2 < KT) load_stage(kt + 2, (kt + 2) % NSTAGE);

            const uint32_t aS = sbase + s * STAGE_B;
            const uint32_t bS = aS + 16384;

            #pragma unroll
            for (int ks = 0; ks < 4; ks++) {
                const int chunk = ks * 32 + (lane >> 4) * 16;
                uint32_t af[2][4];
                #pragma unroll
                for (int mi = 0; mi < 2; mi++) {
                    const int r = wm * 32 + mi * 16 + (lane & 15);
                    ldsm4(af[mi], aS + SWZ128((uint32_t)(r * 128 + chunk)));
                }
                uint32_t bf[4][4];
                #pragma unroll
                for (int ni = 0; ni < 4; ni++) {
                    const int r = wn * 64 + ni * 16 + (lane & 15);
                    ldsm4(bf[ni], bS + SWZ128((uint32_t)(r * 128 + chunk)));
                }
                #pragma unroll
                for (int mi = 0; mi < 2; mi++) {
                    #pragma unroll
                    for (int nj = 0; nj < 8; nj++) {
                        const int ni = nj >> 1, oct = nj & 1;
                        mma16816(acc[mi][nj], af[mi], bf[ni][oct], bf[ni][oct + 2]);
                    }
                }
            }
        }

        // ---- epilogue ----
        float* cf = Cf ? Cf + (long long)b * sC : nullptr;
        f16*   oh = Oh ? Oh + (long long)b * sC : nullptr;
        const int nv = (VAR == 2 && EPI == 2) ? d_nv[b] : 0;

        #pragma unroll
        for (int mi = 0; mi < 2; mi++) {
            #pragma unroll
            for (int nj = 0; nj < 8; nj++) {
                const int row = tileM + wm * 32 + mi * 16 + (lane >> 2);
                const int col = tileN + wn * 64 + nj * 8 + (lane & 3) * 2;
                #pragma unroll
                for (int half = 0; half < 2; half++) {
                    const int r = row + half * 8;
                    float v0 = acc[mi][nj][half * 2];
                    float v1 = acc[mi][nj][half * 2 + 1];
                    if (EPI == 0 || EPI == 1) {
                        v0 += __ldg(bias + col);
                        v1 += __ldg(bias + col + 1);
                    } else if (EPI == 2) {
                        // masked lanes -> large negative; f16 stores -inf,
                        // softmax exp() maps it to exactly 0.
                        v0 = (col     < nv) ? v0 * scale : -1e9f;
                        v1 = (col + 1 < nv) ? v1 * scale : -1e9f;
                    } else if (EPI == 5) {
                        const float bv = __ldg(bias + r);
                        v0 += bv;
                        v1 += bv;
                    }
                    if (EPI == 1) {
                        *(float2*)(cf + (long long)r * N + col) = make_float2(v0, v1);
                    } else {
                        f16 h2[2] = {__float2half_rn(v0), __float2half_rn(v1)};
                        *(uint32_t*)(oh + (long long)r * N + col) = *(uint32_t*)h2;
                    }
                }
            }
        }
        __syncthreads();   // all warps done with epilogue before next tile reuses smem
    }
}

// ============ softmax over compacted row length lkvp[b], fp16 in/out ============
__global__ void __launch_bounds__(256)
softmax_kernel(const f16* __restrict__ S, f16* __restrict__ Ph,
               const int* __restrict__ d_lkvp)
{
    const int b = blockIdx.x >> 10;          // LQ = 1024 rows per batch
    const int len = d_lkvp[b];
    const long long ro = (long long)blockIdx.x * LKV;
    const int tid = threadIdx.x;
    const bool active = (tid * 8) < len;

    float vals[8];
    if (active) {
        uint4 pk = *(const uint4*)(S + ro + tid * 8);
        const f16* hp = (const f16*)&pk;
        #pragma unroll
        for (int i = 0; i < 8; i++) vals[i] = __half2float(hp[i]);
    } else {
        #pragma unroll
        for (int i = 0; i < 8; i++) vals[i] = -1e30f;
    }

    float mx = vals[0];
    #pragma unroll
    for (int i = 1; i < 8; i++) mx = fmaxf(mx, vals[i]);

    __shared__ float red[8];
    #pragma unroll
    for (int o = 16; o > 0; o >>= 1)
        mx = fmaxf(mx, __shfl_xor_sync(0xFFFFFFFFu, mx, o));
    if ((tid & 31) == 0) red[tid >> 5] = mx;
    __syncthreads();
    if (tid == 0) {
        float v = red[0];
        #pragma unroll
        for (int w = 1; w < 8; w++) v = fmaxf(v, red[w]);
        red[0] = v;
    }
    __syncthreads();
    mx = red[0];

    float sum = 0.0f;
    #pragma unroll
    for (int i = 0; i < 8; i++) {
        vals[i] = __expf(vals[i] - mx);   // -inf -> exactly 0
        sum += vals[i];
    }
    __syncthreads();
    #pragma unroll
    for (int o = 16; o > 0; o >>= 1)
        sum += __shfl_xor_sync(0xFFFFFFFFu, sum, o);
    if ((tid & 31) == 0) red[tid >> 5] = sum;
    __syncthreads();
    if (tid == 0) {
        float v = red[0];
        #pragma unroll
        for (int w = 1; w < 8; w++) v += red[w];
        red[0] = v;
    }
    __syncthreads();
    const float inv = 1.0f / red[0];

    if (active) {
        f16 h[8];
        #pragma unroll
        for (int i = 0; i < 8; i++) h[i] = __float2half_rn(vals[i] * inv);
        *(uint4*)(Ph + ro + tid * 8) = *(uint4*)h;
    }
}

// ================= host launcher =================
extern "C" void kernel_launch(void* const* d_in, const int* in_sizes, int n_in,
                              void* d_out, int out_size)
{
    const float* query = (const float*)d_in[0];
    const float* kv    = (const float*)d_in[1];
    const void*  mask  = d_in[2];
    const float* Wq = (const float*)d_in[3];
    const float* bq = (const float*)d_in[4];
    const float* Wk = (const float*)d_in[5];
    const float* bk = (const float*)d_in[6];
    const float* Wv = (const float*)d_in[7];
    const float* bv = (const float*)d_in[8];
    const float* Wo = (const float*)d_in[9];
    const float* bo = (const float*)d_in[10];
    float* out = (float*)d_out;

    f16 *qc, *kvcomp, *WqT, *WkT, *WvT, *WoT;
    f16 *Qh, *Kh, *VT, *Sh, *Ph, *Ch;
    int *NV, *LK;
    cudaGetSymbolAddress((void**)&qc,  g_qc);
    cudaGetSymbolAddress((void**)&kvcomp, g_kvcomp);
    cudaGetSymbolAddress((void**)&WqT, g_WqT);  cudaGetSymbolAddress((void**)&WkT, g_WkT);
    cudaGetSymbolAddress((void**)&WvT, g_WvT);  cudaGetSymbolAddress((void**)&WoT, g_WoT);
    cudaGetSymbolAddress((void**)&Qh, g_Qh);    cudaGetSymbolAddress((void**)&Kh, g_Kh);
    cudaGetSymbolAddress((void**)&VT, g_VT);
    cudaGetSymbolAddress((void**)&Sh, g_Sh);    cudaGetSymbolAddress((void**)&Ph, g_Ph);
    cudaGetSymbolAddress((void**)&Ch, g_Ch);
    cudaGetSymbolAddress((void**)&NV, g_nvalid);
    cudaGetSymbolAddress((void**)&LK, g_lkvp);

    cudaFuncSetAttribute(mma_gemm<0,0>, cudaFuncAttributeMaxDynamicSharedMemorySize, DSMEM_B);
    cudaFuncSetAttribute(mma_gemm<0,1>, cudaFuncAttributeMaxDynamicSharedMemorySize, DSMEM_B);
    cudaFuncSetAttribute(mma_gemm<1,0>, cudaFuncAttributeMaxDynamicSharedMemorySize, DSMEM_B);
    cudaFuncSetAttribute(mma_gemm<2,2>, cudaFuncAttributeMaxDynamicSharedMemorySize, DSMEM_B);
    cudaFuncSetAttribute(mma_gemm<3,3>, cudaFuncAttributeMaxDynamicSharedMemorySize, DSMEM_B);
    cudaFuncSetAttribute(mma_gemm<5,2>, cudaFuncAttributeMaxDynamicSharedMemorySize, DSMEM_B);

    int nsm = 148;
    cudaDeviceGetAttribute(&nsm, cudaDevAttrMultiProcessorCount, 0);
    const int PGRID = nsm * 2;   // one balanced persistent wave (2 CTAs/SM)

    const float scale = 1.0f / 32.0f;  // 1/sqrt(1024)

    // 1. query convert
    convert_kernel<<<(int)(((long long)BATCH * LQ * QDIM / 4 + 255) / 256), 256>>>(
        query, qc, (long long)BATCH * LQ * QDIM / 4);

    // 2. all four weight transposes in one launch
    {
        WTArgs wa;
        wa.src[0] = Wq;  wa.dst[0] = WqT;
        wa.src[1] = Wk;  wa.dst[1] = WkT;
        wa.src[2] = Wv;  wa.dst[2] = WvT;
        wa.src[3] = Wo;  wa.dst[3] = WoT;
        wtrans_kernel<<<dim3(32, 32, 4), dim3(32, 8)>>>(wa);
    }

    // 3. compaction (self-detects mask dtype)
    build_compact_kernel<<<BATCH, 256>>>(mask);

    // 4. Q projection -> Qh   (ncu control)
    mma_gemm<0,0><<<PGRID, 256, DSMEM_B>>>(
        qc, WqT, nullptr, Qh, bq, nullptr, nullptr, 0.0f,
        HID, QDIM, QDIM, QDIM, 0, 0, 0,
        HID / 128, (BATCH * LQ) / 128, 1);

    // 5. gather compacted kv rows (fp16)
    gather_kv_kernel<<<dim3(LKV, BATCH), 128>>>(kv);

    // 6. K projection on compacted rows -> Kh (M limited by lkvp)
    mma_gemm<0,1><<<PGRID, 256, DSMEM_B>>>(
        kvcomp, WkT, nullptr, Kh, bk, NV, LK, 0.0f,
        HID, QDIM, QDIM, QDIM,
        (long long)LKV * QDIM, 0, (long long)LKV * HID,
        HID / 128, LKV / 128, BATCH);

    // 7. V projection directly transposed: VT[b][h][j] (N limited, row bias)
    mma_gemm<5,2><<<PGRID, 256, DSMEM_B>>>(
        WvT, kvcomp, nullptr, VT, bv, NV, LK, 0.0f,
        LKV, QDIM, QDIM, QDIM,
        0, (long long)LKV * QDIM, (long long)HID * LKV,
        LKV / 128, HID / 128, BATCH);

    // 8. scores (compact N): S = Q @ K^T -> f16 (masked lanes -> -inf)
    mma_gemm<2,2><<<PGRID, 256, DSMEM_B>>>(
        Qh, Kh, nullptr, Sh, nullptr, NV, LK, scale,
        LKV, HID, HID, HID,
        (long long)LQ * HID, (long long)LKV * HID, (long long)LQ * LKV,
        LKV / 128, LQ / 128, BATCH);

    // 9. softmax over lkvp[b] -> Ph
    softmax_kernel<<<BATCH * LQ, 256>>>(Sh, Ph, LK);

    // 10. context (runtime K = lkvp[b]): C = P @ VT^T
    mma_gemm<3,3><<<PGRID, 256, DSMEM_B>>>(
        Ph, VT, nullptr, Ch, nullptr, NV, LK, 0.0f,
        HID, 0, LKV, LKV,
        (long long)LQ * LKV, (long long)HID * LKV, (long long)LQ * HID,
        HID / 128, LQ / 128, BATCH);

    // 11. output projection: out = C @ WoT^T + bo (fp32)
    mma_gemm<1,0><<<PGRID, 256, DSMEM_B>>>(
        Ch, WoT, out, nullptr, bo, nullptr, nullptr, 0.0f,
        QDIM, HID, HID, HID, 0, 0, 0,
        QDIM / 128, (BATCH * LQ) / 128, 1);
}

// round 14
// speedup vs baseline: 1.0329x; 1.0044x over previous
#include <cuda_runtime.h>
#include <cuda_fp16.h>
#include <stdint.h>

// Problem constants
#define BATCH 8
#define LQ    1024
#define LKV   2048
#define HID   1024
#define QDIM  1024

typedef __half f16;

// ================= scratch (static device globals) =================
__device__ __align__(16) f16 g_qc [(size_t)BATCH * LQ  * QDIM];   // query fp16
__device__ __align__(16) f16 g_kvcomp[(size_t)BATCH * LKV * QDIM]; // compacted kv fp16
__device__ __align__(16) f16 g_WqT[(size_t)HID * QDIM];
__device__ __align__(16) f16 g_WkT[(size_t)HID * QDIM];
__device__ __align__(16) f16 g_WvT[(size_t)HID * QDIM];
__device__ __align__(16) f16 g_WoT[(size_t)HID * QDIM];
__device__ __align__(16) f16  g_Qh [(size_t)BATCH * LQ  * HID];
__device__ __align__(16) f16  g_Kh [(size_t)BATCH * LKV * HID];   // compacted K
__device__ __align__(16) f16  g_VT [(size_t)BATCH * HID * LKV];   // compacted V^T
__device__ __align__(16) f16  g_Sh [(size_t)BATCH * LQ  * LKV];   // compacted scores (fp16)
__device__ __align__(16) f16  g_Ph [(size_t)BATCH * LQ  * LKV];   // compacted probs
__device__ __align__(16) f16  g_Ch [(size_t)BATCH * LQ  * HID];
__device__ int g_idx[(size_t)BATCH * LKV];   // compaction index
__device__ int g_nvalid[BATCH];
__device__ int g_lkvp[BATCH];                // nvalid rounded up to 128

// ================= PTX helpers =================
__device__ __forceinline__ uint32_t smem_to_u32(const void* p) {
    uint32_t a;
    asm("{ .reg .u64 t; cvta.to.shared.u64 t, %1; cvt.u32.u64 %0, t; }"
        : "=r"(a) : "l"(p));
    return a;
}

#define SWZ128(o) ((o) ^ (((o) >> 3) & 0x70))

__device__ __forceinline__ void cp16(uint32_t saddr, const void* g) {
    asm volatile("cp.async.cg.shared.global [%0], [%1], 16;"
                 :: "r"(saddr), "l"(g) : "memory");
}
#define CP_COMMIT() asm volatile("cp.async.commit_group;" ::: "memory")
#define CP_WAIT1()  asm volatile("cp.async.wait_group 1;" ::: "memory")
#define CP_WAIT0()  asm volatile("cp.async.wait_group 0;" ::: "memory")

__device__ __forceinline__ void ldsm4(uint32_t* r, uint32_t addr) {
    asm volatile("ldmatrix.sync.aligned.m8n8.x4.shared.b16 {%0,%1,%2,%3}, [%4];"
                 : "=r"(r[0]), "=r"(r[1]), "=r"(r[2]), "=r"(r[3]) : "r"(addr));
}

__device__ __forceinline__ void mma16816(float* d, const uint32_t* a,
                                         uint32_t b0, uint32_t b1) {
    asm volatile(
        "mma.sync.aligned.m16n8k16.row.col.f32.f16.f16.f32 "
        "{%0,%1,%2,%3}, {%4,%5,%6,%7}, {%8,%9}, {%0,%1,%2,%3};"
        : "+f"(d[0]), "+f"(d[1]), "+f"(d[2]), "+f"(d[3])
        : "r"(a[0]), "r"(a[1]), "r"(a[2]), "r"(a[3]), "r"(b0), "r"(b1));
}

// ================= fused preprocess kernel =================
// Block ranges (256 threads each):
//   [0, 8)                : per-batch mask compaction (self-detecting dtype)
//   [8, 8+1024)           : weight transposes, 256 blocks per weight (z = idx/256)
//                           tile = 128 rows x 32 cols of the fp32 source
//   [8+1024, 8+1024+8192) : query fp32 -> fp16 convert (float4 granularity)
#define PP_COMPACT 8
#define PP_WT_PER  256
#define PP_WT      (4 * PP_WT_PER)
#define PP_CONV    ((BATCH * LQ * QDIM / 4) / 256)   // 8192
#define PP_TOTAL   (PP_COMPACT + PP_WT + PP_CONV)

struct PPArgs {
    const float* query;
    const void*  mask;
    const float* wsrc[4];
    f16*         wdst[4];
};

__global__ void __launch_bounds__(256)
preprocess_kernel(PPArgs args)
{
    const int bid = blockIdx.x;
    const int tid = threadIdx.x;

    if (bid < PP_COMPACT) {
        // ---- compaction for batch b = bid ----
        const int b = bid;
        const void* mask_raw = args.mask;

        __shared__ int s_bad;
        if (tid == 0) s_bad = 0;
        __syncthreads();
        {
            const int* w = (const int*)mask_raw;
            int bad = 0;
            for (int i = tid; i < 4096; i += 256)
                if ((unsigned)w[i] > 1u) bad = 1;
            if (bad) atomicOr(&s_bad, 1);
        }
        __syncthreads();
        const int is_u8 = s_bad;

        const int base = tid * 8;
        int m[8], cnt = 0;
        #pragma unroll
        for (int i = 0; i < 8; i++) {
            const int gi = b * LKV + base + i;
            int v = is_u8 ? (((const uint8_t*)mask_raw)[gi] != 0)
                          : (((const int*)mask_raw)[gi] != 0);
            m[i] = v;
            cnt += v;
        }

        const int lane = tid & 31, w = tid >> 5;
        int v = cnt;
        #pragma unroll
        for (int o = 1; o < 32; o <<= 1) {
            int t = __shfl_up_sync(0xFFFFFFFFu, v, o);
            if (lane >= o) v += t;
        }
        __shared__ int ws[8];
        if (lane == 31) ws[w] = v;
        __syncthreads();
        __shared__ int total;
        if (tid == 0) {
            int s = 0;
            #pragma unroll
            for (int i = 0; i < 8; i++) { int t = ws[i]; ws[i] = s; s += t; }
            total = s;
        }
        __syncthreads();
        int pos = v - cnt + ws[w];

        #pragma unroll
        for (int i = 0; i < 8; i++)
            if (m[i]) g_idx[b * LKV + pos++] = base + i;

        if (tid == 0) {
            g_nvalid[b] = total;
            g_lkvp[b]   = (total + 127) & ~127;
        }
    } else if (bid < PP_COMPACT + PP_WT) {
        // ---- weight transpose: 1024x1024 fp32 -> fp16 transposed ----
        // tile: 128 source rows (br) x 32 source cols (bc)
        const int t2 = bid - PP_COMPACT;
        const int z  = t2 / PP_WT_PER;
        const int ti = t2 - z * PP_WT_PER;     // 0..255: 8 r-tiles x 32 c-tiles
        const int br = (ti & 7) * 128;
        const int bc = (ti >> 3) * 32;
        const float* x = args.wsrc[z];
        f16*        th = args.wdst[z];

        __shared__ float t[32][129];   // [c][r] transposed staging

        // load: 4 passes, each thread one float4 (fully coalesced)
        #pragma unroll
        for (int p = 0; p < 4; p++) {
            const int r  = p * 32 + (tid >> 3);
            const int c4 = (tid & 7) * 4;
            float4 vv = *(const float4*)(x + (long long)(br + r) * 1024 + bc + c4);
            t[c4 + 0][r] = vv.x;
            t[c4 + 1][r] = vv.y;
            t[c4 + 2][r] = vv.z;
            t[c4 + 3][r] = vv.w;
        }
        __syncthreads();

        // store: thread -> 16 consecutive output halves (2 x uint4, coalesced)
        const int c  = tid >> 3;
        const int r0 = (tid & 7) * 16;
        f16 h[16];
        #pragma unroll
        for (int i = 0; i < 16; i++) h[i] = __float2half_rn(t[c][r0 + i]);
        f16* op = th + (long long)(bc + c) * 1024 + br + r0;
        *(uint4*)(op)     = *(uint4*)(h);
        *(uint4*)(op + 8) = *(uint4*)(h + 8);
    } else {
        // ---- query fp32 -> fp16 convert ----
        const long long i = (long long)(bid - PP_COMPACT - PP_WT) * 256 + tid;
        float4 v = *(const float4*)(args.query + i * 4);
        f16 hh[4] = {__float2half_rn(v.x), __float2half_rn(v.y),
                     __float2half_rn(v.z), __float2half_rn(v.w)};
        f16* qc = g_qc;
        *(uint2*)(qc + i * 4) = *(uint2*)hh;
    }
}

// Gather + fp32->fp16 convert: kvcomp[b][j] = kv[b][idx[b][j]] ; pad rows = 0.
__global__ void __launch_bounds__(128)
gather_kv_kernel(const float* __restrict__ kv)
{
    const int j = blockIdx.x, b = blockIdx.y, t = threadIdx.x;
    if (j >= g_lkvp[b]) return;
    f16* dst = g_kvcomp + ((size_t)b * LKV + j) * QDIM;
    if (j < g_nvalid[b]) {
        const float* src = kv + ((size_t)b * LKV + g_idx[b * LKV + j]) * QDIM;
        float4 a = *(const float4*)(src + t * 8);
        float4 c = *(const float4*)(src + t * 8 + 4);
        f16 h[8] = {__float2half_rn(a.x), __float2half_rn(a.y),
                    __float2half_rn(a.z), __float2half_rn(a.w),
                    __float2half_rn(c.x), __float2half_rn(c.y),
                    __float2half_rn(c.z), __float2half_rn(c.w)};
        *(uint4*)(dst + t * 8) = *(uint4*)h;
    } else {
        *(uint4*)(dst + t * 8) = make_uint4(0, 0, 0, 0);
    }
}

// ================= persistent single-pass fp16 HMMA GEMM =================
// C[M,N] = A[M,K] @ B[N,K]^T, fp32 accumulate.
// CTA 128x128 tile, K-tile 64, 8 warps (4M x 2N), 3-stage cp.async pipeline.
// Persistent: 1-D grid strides over linearized (gz, gy, gx) tile space.
// EPI: 0=+bias[col]->f16 ; 1=+bias[col]->fp32 ; 2=compact mask*scale->f16 ;
//      3=plain->f16 ; 5=+bias[row]->f16 (transposed projection)
// VAR: 0=none ; 1=M limited by lkvp[b] ; 2=N limited (EPI2 masks by nvalid) ;
//      3=K runtime = lkvp[b]
#define BKT 64
#define STAGE_B 32768
#define NSTAGE 3
#define DSMEM_B (NSTAGE * STAGE_B)   // 96KB

template <int EPI, int VAR>
__global__ void __launch_bounds__(256, 2)
mma_gemm(const f16* __restrict__ A, const f16* __restrict__ B,
         float* __restrict__ Cf, f16* __restrict__ Oh,
         const float* __restrict__ bias,
         const int* __restrict__ d_nv, const int* __restrict__ d_lkvp,
         float scale, int N, int KdHost, int ldA, int ldB,
         long long sA, long long sB, long long sC,
         int gx, int gy, int gz)
{
    extern __shared__ char smem[];
    const uint32_t sbase = smem_to_u32(smem);

    const int tid  = threadIdx.x;
    const int wid = tid >> 5, lane = tid & 31;
    const int wm = wid & 3;
    const int wn = wid >> 2;
    const int ntiles = gx * gy * gz;

    for (int t = blockIdx.x; t < ntiles; t += gridDim.x) {
        const int b  = t / (gx * gy);
        const int r2 = t - b * (gx * gy);
        const int ty = r2 / gx;
        const int tx = r2 - ty * gx;
        const int tileM = ty * 128;
        const int tileN = tx * 128;

        int lim = 0;
        if (VAR != 0) lim = d_lkvp[b];
        if (VAR == 1 && tileM >= lim) continue;
        if (VAR == 2 && tileN >= lim) continue;
        const int Kd = (VAR == 3) ? lim : KdHost;

        const f16* baseA = A + (long long)b * sA + (long long)tileM * ldA;
        const f16* baseB = B + (long long)b * sB + (long long)tileN * ldB;

        float acc[2][8][4];
        #pragma unroll
        for (int mi = 0; mi < 2; mi++)
            #pragma unroll
            for (int nj = 0; nj < 8; nj++)
                #pragma unroll
                for (int q = 0; q < 4; q++) acc[mi][nj][q] = 0.0f;

        const int KT = Kd / BKT;

        auto load_stage = [&](int kt, int s) {
            const int k0 = kt * BKT;
            #pragma unroll
            for (int sub = 0; sub < 2; sub++) {
                const f16* gb = sub ? baseB : baseA;
                const int ld  = sub ? ldB : ldA;
                const uint32_t so = sbase + s * STAGE_B + sub * 16384;
                #pragma unroll
                for (int i = 0; i < 4; i++) {
                    const int c  = i * 256 + tid;
                    const int r  = c >> 3;
                    const int kc = c & 7;
                    cp16(so + SWZ128((uint32_t)(r * 128 + kc * 16)),
                         gb + (long long)r * ld + k0 + kc * 8);
                }
            }
            CP_COMMIT();
        };

        load_stage(0, 0);
        if (KT > 1) load_stage(1, 1);

        for (int kt = 0; kt < KT; kt++) {
            const int s = kt % NSTAGE;
            if (kt + 1 < KT) CP_WAIT1(); else CP_WAIT0();
            __syncthreads();
            if (kt + 2 < KT) load_stage(kt + 2, (kt + 2) % NSTAGE);

            const uint32_t aS = sbase + s * STAGE_B;
            const uint32_t bS = aS + 16384;

            #pragma unroll
            for (int ks = 0; ks < 4; ks++) {
                const int chunk = ks * 32 + (lane >> 4) * 16;
                uint32_t af[2][4];
                #pragma unroll
                for (int mi = 0; mi < 2; mi++) {
                    const int r = wm * 32 + mi * 16 + (lane & 15);
                    ldsm4(af[mi], aS + SWZ128((uint32_t)(r * 128 + chunk)));
                }
                uint32_t bf[4][4];
                #pragma unroll
                for (int ni = 0; ni < 4; ni++) {
                    const int r = wn * 64 + ni * 16 + (lane & 15);
                    ldsm4(bf[ni], bS + SWZ128((uint32_t)(r * 128 + chunk)));
                }
                #pragma unroll
                for (int mi = 0; mi < 2; mi++) {
                    #pragma unroll
                    for (int nj = 0; nj < 8; nj++) {
                        const int ni = nj >> 1, oct = nj & 1;
                        mma16816(acc[mi][nj], af[mi], bf[ni][oct], bf[ni][oct + 2]);
                    }
                }
            }
        }

        // ---- epilogue ----
        float* cf = Cf ? Cf + (long long)b * sC : nullptr;
        f16*   oh = Oh ? Oh + (long long)b * sC : nullptr;
        const int nv = (VAR == 2 && EPI == 2) ? d_nv[b] : 0;

        #pragma unroll
        for (int mi = 0; mi < 2; mi++) {
            #pragma unroll
            for (int nj = 0; nj < 8; nj++) {
                const int row = tileM + wm * 32 + mi * 16 + (lane >> 2);
                const int col = tileN + wn * 64 + nj * 8 + (lane & 3) * 2;
                #pragma unroll
                for (int half = 0; half < 2; half++) {
                    const int r = row + half * 8;
                    float v0 = acc[mi][nj][half * 2];
                    float v1 = acc[mi][nj][half * 2 + 1];
                    if (EPI == 0 || EPI == 1) {
                        v0 += __ldg(bias + col);
                        v1 += __ldg(bias + col + 1);
                    } else if (EPI == 2) {
                        v0 = (col     < nv) ? v0 * scale : -1e9f;
                        v1 = (col + 1 < nv) ? v1 * scale : -1e9f;
                    } else if (EPI == 5) {
                        const float bv = __ldg(bias + r);
                        v0 += bv;
                        v1 += bv;
                    }
                    if (EPI == 1) {
                        *(float2*)(cf + (long long)r * N + col) = make_float2(v0, v1);
                    } else {
                        f16 h2[2] = {__float2half_rn(v0), __float2half_rn(v1)};
                        *(uint32_t*)(oh + (long long)r * N + col) = *(uint32_t*)h2;
                    }
                }
            }
        }
        __syncthreads();   // all warps done with epilogue before next tile reuses smem
    }
}

// ============ softmax over compacted row length lkvp[b], fp16 in/out ============
__global__ void __launch_bounds__(256)
softmax_kernel(const f16* __restrict__ S, f16* __restrict__ Ph,
               const int* __restrict__ d_lkvp)
{
    const int b = blockIdx.x >> 10;          // LQ = 1024 rows per batch
    const int len = d_lkvp[b];
    const long long ro = (long long)blockIdx.x * LKV;
    const int tid = threadIdx.x;
    const bool active = (tid * 8) < len;

    float vals[8];
    if (active) {
        uint4 pk = *(const uint4*)(S + ro + tid * 8);
        const f16* hp = (const f16*)&pk;
        #pragma unroll
        for (int i = 0; i < 8; i++) vals[i] = __half2float(hp[i]);
    } else {
        #pragma unroll
        for (int i = 0; i < 8; i++) vals[i] = -1e30f;
    }

    float mx = vals[0];
    #pragma unroll
    for (int i = 1; i < 8; i++) mx = fmaxf(mx, vals[i]);

    __shared__ float red[8];
    #pragma unroll
    for (int o = 16; o > 0; o >>= 1)
        mx = fmaxf(mx, __shfl_xor_sync(0xFFFFFFFFu, mx, o));
    if ((tid & 31) == 0) red[tid >> 5] = mx;
    __syncthreads();
    if (tid == 0) {
        float v = red[0];
        #pragma unroll
        for (int w = 1; w < 8; w++) v = fmaxf(v, red[w]);
        red[0] = v;
    }
    __syncthreads();
    mx = red[0];

    float sum = 0.0f;
    #pragma unroll
    for (int i = 0; i < 8; i++) {
        vals[i] = __expf(vals[i] - mx);   // -inf -> exactly 0
        sum += vals[i];
    }
    __syncthreads();
    #pragma unroll
    for (int o = 16; o > 0; o >>= 1)
        sum += __shfl_xor_sync(0xFFFFFFFFu, sum, o);
    if ((tid & 31) == 0) red[tid >> 5] = sum;
    __syncthreads();
    if (tid == 0) {
        float v = red[0];
        #pragma unroll
        for (int w = 1; w < 8; w++) v += red[w];
        red[0] = v;
    }
    __syncthreads();
    const float inv = 1.0f / red[0];

    if (active) {
        f16 h[8];
        #pragma unroll
        for (int i = 0; i < 8; i++) h[i] = __float2half_rn(vals[i] * inv);
        *(uint4*)(Ph + ro + tid * 8) = *(uint4*)h;
    }
}

// ================= host launcher =================
extern "C" void kernel_launch(void* const* d_in, const int* in_sizes, int n_in,
                              void* d_out, int out_size)
{
    const float* query = (const float*)d_in[0];
    const float* kv    = (const float*)d_in[1];
    const void*  mask  = d_in[2];
    const float* Wq = (const float*)d_in[3];
    const float* bq = (const float*)d_in[4];
    const float* Wk = (const float*)d_in[5];
    const float* bk = (const float*)d_in[6];
    const float* Wv = (const float*)d_in[7];
    const float* bv = (const float*)d_in[8];
    const float* Wo = (const float*)d_in[9];
    const float* bo = (const float*)d_in[10];
    float* out = (float*)d_out;

    f16 *qc, *kvcomp, *WqT, *WkT, *WvT, *WoT;
    f16 *Qh, *Kh, *VT, *Sh, *Ph, *Ch;
    int *NV, *LK;
    cudaGetSymbolAddress((void**)&qc,  g_qc);
    cudaGetSymbolAddress((void**)&kvcomp, g_kvcomp);
    cudaGetSymbolAddress((void**)&WqT, g_WqT);  cudaGetSymbolAddress((void**)&WkT, g_WkT);
    cudaGetSymbolAddress((void**)&WvT, g_WvT);  cudaGetSymbolAddress((void**)&WoT, g_WoT);
    cudaGetSymbolAddress((void**)&Qh, g_Qh);    cudaGetSymbolAddress((void**)&Kh, g_Kh);
    cudaGetSymbolAddress((void**)&VT, g_VT);
    cudaGetSymbolAddress((void**)&Sh, g_Sh);    cudaGetSymbolAddress((void**)&Ph, g_Ph);
    cudaGetSymbolAddress((void**)&Ch, g_Ch);
    cudaGetSymbolAddress((void**)&NV, g_nvalid);
    cudaGetSymbolAddress((void**)&LK, g_lkvp);

    cudaFuncSetAttribute(mma_gemm<0,0>, cudaFuncAttributeMaxDynamicSharedMemorySize, DSMEM_B);
    cudaFuncSetAttribute(mma_gemm<0,1>, cudaFuncAttributeMaxDynamicSharedMemorySize, DSMEM_B);
    cudaFuncSetAttribute(mma_gemm<1,0>, cudaFuncAttributeMaxDynamicSharedMemorySize, DSMEM_B);
    cudaFuncSetAttribute(mma_gemm<2,2>, cudaFuncAttributeMaxDynamicSharedMemorySize, DSMEM_B);
    cudaFuncSetAttribute(mma_gemm<3,3>, cudaFuncAttributeMaxDynamicSharedMemorySize, DSMEM_B);
    cudaFuncSetAttribute(mma_gemm<5,2>, cudaFuncAttributeMaxDynamicSharedMemorySize, DSMEM_B);

    int nsm = 148;
    cudaDeviceGetAttribute(&nsm, cudaDevAttrMultiProcessorCount, 0);
    const int PGRID = nsm * 2;   // one balanced persistent wave (2 CTAs/SM)

    const float scale = 1.0f / 32.0f;  // 1/sqrt(1024)

    // 1. fused preprocess: compaction + 4x weight transpose + query convert
    {
        PPArgs pa;
        pa.query = query;
        pa.mask  = mask;
        pa.wsrc[0] = Wq;  pa.wdst[0] = WqT;
        pa.wsrc[1] = Wk;  pa.wdst[1] = WkT;
        pa.wsrc[2] = Wv;  pa.wdst[2] = WvT;
        pa.wsrc[3] = Wo;  pa.wdst[3] = WoT;
        preprocess_kernel<<<PP_TOTAL, 256>>>(pa);
    }

    // 2. gather compacted kv rows (fp16)
    gather_kv_kernel<<<dim3(LKV, BATCH), 128>>>(kv);

    // 3. (small gap) keep GEMM as 4th-ish launch for ncu comparability
    // 4. Q projection -> Qh   (ncu control)
    mma_gemm<0,0><<<PGRID, 256, DSMEM_B>>>(
        qc, WqT, nullptr, Qh, bq, nullptr, nullptr, 0.0f,
        HID, QDIM, QDIM, QDIM, 0, 0, 0,
        HID / 128, (BATCH * LQ) / 128, 1);

    // 5. K projection on compacted rows -> Kh (M limited by lkvp)
    mma_gemm<0,1><<<PGRID, 256, DSMEM_B>>>(
        kvcomp, WkT, nullptr, Kh, bk, NV, LK, 0.0f,
        HID, QDIM, QDIM, QDIM,
        (long long)LKV * QDIM, 0, (long long)LKV * HID,
        HID / 128, LKV / 128, BATCH);

    // 6. V projection directly transposed: VT[b][h][j] (N limited, row bias)
    mma_gemm<5,2><<<PGRID, 256, DSMEM_B>>>(
        WvT, kvcomp, nullptr, VT, bv, NV, LK, 0.0f,
        LKV, QDIM, QDIM, QDIM,
        0, (long long)LKV * QDIM, (long long)HID * LKV,
        LKV / 128, HID / 128, BATCH);

    // 7. scores (compact N): S = Q @ K^T -> f16 (masked lanes -> -inf)
    mma_gemm<2,2><<<PGRID, 256, DSMEM_B>>>(
        Qh, Kh, nullptr, Sh, nullptr, NV, LK, scale,
        LKV, HID, HID, HID,
        (long long)LQ * HID, (long long)LKV * HID, (long long)LQ * LKV,
        LKV / 128, LQ / 128, BATCH);

    // 8. softmax over lkvp[b] -> Ph
    softmax_kernel<<<BATCH * LQ, 256>>>(Sh, Ph, LK);

    // 9. context (runtime K = lkvp[b]): C = P @ VT^T
    mma_gemm<3,3><<<PGRID, 256, DSMEM_B>>>(
        Ph, VT, nullptr, Ch, nullptr, NV, LK, 0.0f,
        HID, 0, LKV, LKV,
        (long long)LQ * LKV, (long long)HID * LKV, (long long)LQ * HID,
        HID / 128, LQ / 128, BATCH);

    // 10. output projection: out = C @ WoT^T + bo (fp32)
    mma_gemm<1,0><<<PGRID, 256, DSMEM_B>>>(
        Ch, WoT, out, nullptr, bo, nullptr, nullptr, 0.0f,
        QDIM, HID, HID, HID, 0, 0, 0,
        QDIM / 128, (BATCH * LQ) / 128, 1);
}

// round 15
// speedup vs baseline: 1.1323x; 1.0962x over previous
#include <cuda_runtime.h>
#include <cuda_fp16.h>
#include <stdint.h>

// Problem constants
#define BATCH 8
#define LQ    1024
#define LKV   2048
#define HID   1024
#define QDIM  1024

typedef __half f16;

// ================= scratch (static device globals) =================
__device__ __align__(16) f16 g_qc [(size_t)BATCH * LQ  * QDIM];   // query fp16
__device__ __align__(16) f16 g_kvcomp[(size_t)BATCH * LKV * QDIM]; // compacted kv fp16
__device__ __align__(16) f16 g_WqT[(size_t)HID * QDIM];
__device__ __align__(16) f16 g_WkT[(size_t)HID * QDIM];
__device__ __align__(16) f16 g_WvT[(size_t)HID * QDIM];
__device__ __align__(16) f16 g_WoT[(size_t)HID * QDIM];
__device__ __align__(16) f16  g_Qh [(size_t)BATCH * LQ  * HID];
__device__ __align__(16) f16  g_Kh [(size_t)BATCH * LKV * HID];   // compacted K
__device__ __align__(16) f16  g_VT [(size_t)BATCH * HID * LKV];   // compacted V^T
__device__ __align__(16) f16  g_Sh [(size_t)BATCH * LQ  * LKV];   // compacted scores (fp16)
__device__ __align__(16) f16  g_Ph [(size_t)BATCH * LQ  * LKV];   // compacted probs
__device__ __align__(16) f16  g_Ch [(size_t)BATCH * LQ  * HID];
__device__ int g_idx[(size_t)BATCH * LKV];   // compaction index
__device__ int g_nvalid[BATCH];
__device__ int g_lkvp[BATCH];                // nvalid rounded up to 128

// ================= PTX helpers =================
__device__ __forceinline__ uint32_t smem_to_u32(const void* p) {
    uint32_t a;
    asm("{ .reg .u64 t; cvta.to.shared.u64 t, %1; cvt.u32.u64 %0, t; }"
        : "=r"(a) : "l"(p));
    return a;
}

#define SWZ128(o) ((o) ^ (((o) >> 3) & 0x70))

__device__ __forceinline__ void cp16(uint32_t saddr, const void* g) {
    asm volatile("cp.async.cg.shared.global [%0], [%1], 16;"
                 :: "r"(saddr), "l"(g) : "memory");
}
#define CP_COMMIT() asm volatile("cp.async.commit_group;" ::: "memory")
#define CP_WAIT1()  asm volatile("cp.async.wait_group 1;" ::: "memory")
#define CP_WAIT0()  asm volatile("cp.async.wait_group 0;" ::: "memory")

__device__ __forceinline__ void ldsm4(uint32_t* r, uint32_t addr) {
    asm volatile("ldmatrix.sync.aligned.m8n8.x4.shared.b16 {%0,%1,%2,%3}, [%4];"
                 : "=r"(r[0]), "=r"(r[1]), "=r"(r[2]), "=r"(r[3]) : "r"(addr));
}

__device__ __forceinline__ void mma16816(float* d, const uint32_t* a,
                                         uint32_t b0, uint32_t b1) {
    asm volatile(
        "mma.sync.aligned.m16n8k16.row.col.f32.f16.f16.f32 "
        "{%0,%1,%2,%3}, {%4,%5,%6,%7}, {%8,%9}, {%0,%1,%2,%3};"
        : "+f"(d[0]), "+f"(d[1]), "+f"(d[2]), "+f"(d[3])
        : "r"(a[0]), "r"(a[1]), "r"(a[2]), "r"(a[3]), "r"(b0), "r"(b1));
}

// ================= fused preprocess kernel =================
// Block ranges (256 threads each):
//   [0, 8)                : per-batch mask compaction (self-detecting dtype)
//   [8, 8+1024)           : weight transposes, 256 blocks per weight
//   [8+1024, +8192)       : query fp32 -> fp16 convert
#define PP_COMPACT 8
#define PP_WT_PER  256
#define PP_WT      (4 * PP_WT_PER)
#define PP_CONV    ((BATCH * LQ * QDIM / 4) / 256)   // 8192
#define PP_TOTAL   (PP_COMPACT + PP_WT + PP_CONV)

struct PPArgs {
    const float* query;
    const void*  mask;
    const float* wsrc[4];
    f16*         wdst[4];
};

__global__ void __launch_bounds__(256)
preprocess_kernel(PPArgs args)
{
    const int bid = blockIdx.x;
    const int tid = threadIdx.x;

    if (bid < PP_COMPACT) {
        // ---- compaction for batch b = bid ----
        const int b = bid;
        const void* mask_raw = args.mask;

        __shared__ int s_bad;
        if (tid == 0) s_bad = 0;
        __syncthreads();
        {
            const int* w = (const int*)mask_raw;
            int bad = 0;
            for (int i = tid; i < 4096; i += 256)
                if ((unsigned)w[i] > 1u) bad = 1;
            if (bad) atomicOr(&s_bad, 1);
        }
        __syncthreads();
        const int is_u8 = s_bad;

        const int base = tid * 8;
        int m[8], cnt = 0;
        #pragma unroll
        for (int i = 0; i < 8; i++) {
            const int gi = b * LKV + base + i;
            int v = is_u8 ? (((const uint8_t*)mask_raw)[gi] != 0)
                          : (((const int*)mask_raw)[gi] != 0);
            m[i] = v;
            cnt += v;
        }

        const int lane = tid & 31, w = tid >> 5;
        int v = cnt;
        #pragma unroll
        for (int o = 1; o < 32; o <<= 1) {
            int t = __shfl_up_sync(0xFFFFFFFFu, v, o);
            if (lane >= o) v += t;
        }
        __shared__ int ws[8];
        if (lane == 31) ws[w] = v;
        __syncthreads();
        __shared__ int total;
        if (tid == 0) {
            int s = 0;
            #pragma unroll
            for (int i = 0; i < 8; i++) { int t = ws[i]; ws[i] = s; s += t; }
            total = s;
        }
        __syncthreads();
        int pos = v - cnt + ws[w];

        #pragma unroll
        for (int i = 0; i < 8; i++)
            if (m[i]) g_idx[b * LKV + pos++] = base + i;

        if (tid == 0) {
            g_nvalid[b] = total;
            g_lkvp[b]   = (total + 127) & ~127;
        }
    } else if (bid < PP_COMPACT + PP_WT) {
        // ---- weight transpose: 1024x1024 fp32 -> fp16 transposed ----
        const int t2 = bid - PP_COMPACT;
        const int z  = t2 / PP_WT_PER;
        const int ti = t2 - z * PP_WT_PER;
        const int br = (ti & 7) * 128;
        const int bc = (ti >> 3) * 32;
        const float* x = args.wsrc[z];
        f16*        th = args.wdst[z];

        __shared__ float t[32][129];

        #pragma unroll
        for (int p = 0; p < 4; p++) {
            const int r  = p * 32 + (tid >> 3);
            const int c4 = (tid & 7) * 4;
            float4 vv = *(const float4*)(x + (long long)(br + r) * 1024 + bc + c4);
            t[c4 + 0][r] = vv.x;
            t[c4 + 1][r] = vv.y;
            t[c4 + 2][r] = vv.z;
            t[c4 + 3][r] = vv.w;
        }
        __syncthreads();

        const int c  = tid >> 3;
        const int r0 = (tid & 7) * 16;
        f16 h[16];
        #pragma unroll
        for (int i = 0; i < 16; i++) h[i] = __float2half_rn(t[c][r0 + i]);
        f16* op = th + (long long)(bc + c) * 1024 + br + r0;
        *(uint4*)(op)     = *(uint4*)(h);
        *(uint4*)(op + 8) = *(uint4*)(h + 8);
    } else {
        // ---- query fp32 -> fp16 convert ----
        const long long i = (long long)(bid - PP_COMPACT - PP_WT) * 256 + tid;
        float4 v = *(const float4*)(args.query + i * 4);
        f16 hh[4] = {__float2half_rn(v.x), __float2half_rn(v.y),
                     __float2half_rn(v.z), __float2half_rn(v.w)};
        f16* qc = g_qc;
        *(uint2*)(qc + i * 4) = *(uint2*)hh;
    }
}

// Gather + fp32->fp16 convert: kvcomp[b][j] = kv[b][idx[b][j]] ; pad rows = 0.
__global__ void __launch_bounds__(128)
gather_kv_kernel(const float* __restrict__ kv)
{
    const int j = blockIdx.x, b = blockIdx.y, t = threadIdx.x;
    if (j >= g_lkvp[b]) return;
    f16* dst = g_kvcomp + ((size_t)b * LKV + j) * QDIM;
    if (j < g_nvalid[b]) {
        const float* src = kv + ((size_t)b * LKV + g_idx[b * LKV + j]) * QDIM;
        float4 a = *(const float4*)(src + t * 8);
        float4 c = *(const float4*)(src + t * 8 + 4);
        f16 h[8] = {__float2half_rn(a.x), __float2half_rn(a.y),
                    __float2half_rn(a.z), __float2half_rn(a.w),
                    __float2half_rn(c.x), __float2half_rn(c.y),
                    __float2half_rn(c.z), __float2half_rn(c.w)};
        *(uint4*)(dst + t * 8) = *(uint4*)h;
    } else {
        *(uint4*)(dst + t * 8) = make_uint4(0, 0, 0, 0);
    }
}

// ================= persistent single-pass fp16 HMMA GEMM =================
// C[M,N] = A[M,K] @ B[N,K]^T, fp32 accumulate.
// CTA 128x128 tile, K-tile 64, 8 warps (4M x 2N), 3-stage cp.async pipeline.
// Persistent grid-stride over a DENSE live-tile index:
//   VAR=0: full gz*gy*gx space.
//   VAR=1: M limited by lkvp[b] -> live tiles per batch = (lkvp/128)*gx.
//   VAR=2: N limited by lkvp[b] -> live tiles per batch = gy*(lkvp/128).
//   VAR=3: K runtime = lkvp[b]; full tile space.
// EPI: 0=+bias[col]->f16 ; 1=+bias[col]->fp32 ; 2=compact mask*scale->f16 ;
//      3=plain->f16 ; 5=+bias[row]->f16 (transposed projection)
#define BKT 64
#define STAGE_B 32768
#define NSTAGE 3
#define DSMEM_B (NSTAGE * STAGE_B)   // 96KB

template <int EPI, int VAR>
__global__ void __launch_bounds__(256, 2)
mma_gemm(const f16* __restrict__ A, const f16* __restrict__ B,
         float* __restrict__ Cf, f16* __restrict__ Oh,
         const float* __restrict__ bias,
         const int* __restrict__ d_nv, const int* __restrict__ d_lkvp,
         float scale, int N, int KdHost, int ldA, int ldB,
         long long sA, long long sB, long long sC,
         int gx, int gy, int gz)
{
    extern __shared__ char smem[];
    const uint32_t sbase = smem_to_u32(smem);

    const int tid  = threadIdx.x;
    const int wid = tid >> 5, lane = tid & 31;
    const int wm = wid & 3;
    const int wn = wid >> 2;

    // ---- dense live-tile linearization ----
    int cum[BATCH + 1];
    int ntiles;
    if (VAR == 1 || VAR == 2) {
        int s = 0;
        for (int b2 = 0; b2 < gz; b2++) {
            cum[b2] = s;
            const int c = d_lkvp[b2] >> 7;       // live 128-tiles along limited dim
            s += (VAR == 1) ? c * gx : gy * c;
        }
        cum[gz] = s;
        ntiles = s;
    } else {
        ntiles = gx * gy * gz;
    }

    for (int t = blockIdx.x; t < ntiles; t += gridDim.x) {
        int b, ty, tx;
        if (VAR == 1 || VAR == 2) {
            b = 0;
            while (t >= cum[b + 1]) b++;
            const int local = t - cum[b];
            if (VAR == 1) {
                ty = local / gx;
                tx = local - ty * gx;
            } else {
                const int nt = d_lkvp[b] >> 7;
                ty = local / nt;
                tx = local - ty * nt;
            }
        } else {
            b = t / (gx * gy);
            const int r2 = t - b * (gx * gy);
            ty = r2 / gx;
            tx = r2 - ty * gx;
        }
        const int tileM = ty * 128;
        const int tileN = tx * 128;
        const int Kd = (VAR == 3) ? d_lkvp[b] : KdHost;

        const f16* baseA = A + (long long)b * sA + (long long)tileM * ldA;
        const f16* baseB = B + (long long)b * sB + (long long)tileN * ldB;

        float acc[2][8][4];
        #pragma unroll
        for (int mi = 0; mi < 2; mi++)
            #pragma unroll
            for (int nj = 0; nj < 8; nj++)
                #pragma unroll
                for (int q = 0; q < 4; q++) acc[mi][nj][q] = 0.0f;

        const int KT = Kd / BKT;

        auto load_stage = [&](int kt, int s) {
            const int k0 = kt * BKT;
            #pragma unroll
            for (int sub = 0; sub < 2; sub++) {
                const f16* gb = sub ? baseB : baseA;
                const int ld  = sub ? ldB : ldA;
                const uint32_t so = sbase + s * STAGE_B + sub * 16384;
                #pragma unroll
                for (int i = 0; i < 4; i++) {
                    const int c  = i * 256 + tid;
                    const int r  = c >> 3;
                    const int kc = c & 7;
                    cp16(so + SWZ128((uint32_t)(r * 128 + kc * 16)),
                         gb + (long long)r * ld + k0 + kc * 8);
                }
            }
            CP_COMMIT();
        };

        load_stage(0, 0);
        if (KT > 1) load_stage(1, 1);

        for (int kt = 0; kt < KT; kt++) {
            const int s = kt % NSTAGE;
            if (kt + 1 < KT) CP_WAIT1(); else CP_WAIT0();
            __syncthreads();
            if (kt + 2 < KT) load_stage(kt + 2, (kt + 2) % NSTAGE);

            const uint32_t aS = sbase + s * STAGE_B;
            const uint32_t bS = aS + 16384;

            #pragma unroll
            for (int ks = 0; ks < 4; ks++) {
                const int chunk = ks * 32 + (lane >> 4) * 16;
                uint32_t af[2][4];
                #pragma unroll
                for (int mi = 0; mi < 2; mi++) {
                    const int r = wm * 32 + mi * 16 + (lane & 15);
                    ldsm4(af[mi], aS + SWZ128((uint32_t)(r * 128 + chunk)));
                }
                uint32_t bf[4][4];
                #pragma unroll
                for (int ni = 0; ni < 4; ni++) {
                    const int r = wn * 64 + ni * 16 + (lane & 15);
                    ldsm4(bf[ni], bS + SWZ128((uint32_t)(r * 128 + chunk)));
                }
                #pragma unroll
                for (int mi = 0; mi < 2; mi++) {
                    #pragma unroll
                    for (int nj = 0; nj < 8; nj++) {
                        const int ni = nj >> 1, oct = nj & 1;
                        mma16816(acc[mi][nj], af[mi], bf[ni][oct], bf[ni][oct + 2]);
                    }
                }
            }
        }

        // ---- epilogue ----
        float* cf = Cf ? Cf + (long long)b * sC : nullptr;
        f16*   oh = Oh ? Oh + (long long)b * sC : nullptr;
        const int nv = (VAR == 2 && EPI == 2) ? d_nv[b] : 0;

        #pragma unroll
        for (int mi = 0; mi < 2; mi++) {
            #pragma unroll
            for (int nj = 0; nj < 8; nj++) {
                const int row = tileM + wm * 32 + mi * 16 + (lane >> 2);
                const int col = tileN + wn * 64 + nj * 8 + (lane & 3) * 2;
                #pragma unroll
                for (int half = 0; half < 2; half++) {
                    const int r = row + half * 8;
                    float v0 = acc[mi][nj][half * 2];
                    float v1 = acc[mi][nj][half * 2 + 1];
                    if (EPI == 0 || EPI == 1) {
                        v0 += __ldg(bias + col);
                        v1 += __ldg(bias + col + 1);
                    } else if (EPI == 2) {
                        v0 = (col     < nv) ? v0 * scale : -1e9f;
                        v1 = (col + 1 < nv) ? v1 * scale : -1e9f;
                    } else if (EPI == 5) {
                        const float bv = __ldg(bias + r);
                        v0 += bv;
                        v1 += bv;
                    }
                    if (EPI == 1) {
                        *(float2*)(cf + (long long)r * N + col) = make_float2(v0, v1);
                    } else {
                        f16 h2[2] = {__float2half_rn(v0), __float2half_rn(v1)};
                        *(uint32_t*)(oh + (long long)r * N + col) = *(uint32_t*)h2;
                    }
                }
            }
        }
        __syncthreads();   // all warps done with epilogue before next tile reuses smem
    }
}

// ============ softmax over compacted row length lkvp[b], fp16 in/out ============
__global__ void __launch_bounds__(256)
softmax_kernel(const f16* __restrict__ S, f16* __restrict__ Ph,
               const int* __restrict__ d_lkvp)
{
    const int b = blockIdx.x >> 10;          // LQ = 1024 rows per batch
    const int len = d_lkvp[b];
    const long long ro = (long long)blockIdx.x * LKV;
    const int tid = threadIdx.x;
    const bool active = (tid * 8) < len;

    float vals[8];
    if (active) {
        uint4 pk = *(const uint4*)(S + ro + tid * 8);
        const f16* hp = (const f16*)&pk;
        #pragma unroll
        for (int i = 0; i < 8; i++) vals[i] = __half2float(hp[i]);
    } else {
        #pragma unroll
        for (int i = 0; i < 8; i++) vals[i] = -1e30f;
    }

    float mx = vals[0];
    #pragma unroll
    for (int i = 1; i < 8; i++) mx = fmaxf(mx, vals[i]);

    __shared__ float red[8];
    #pragma unroll
    for (int o = 16; o > 0; o >>= 1)
        mx = fmaxf(mx, __shfl_xor_sync(0xFFFFFFFFu, mx, o));
    if ((tid & 31) == 0) red[tid >> 5] = mx;
    __syncthreads();
    if (tid == 0) {
        float v = red[0];
        #pragma unroll
        for (int w = 1; w < 8; w++) v = fmaxf(v, red[w]);
        red[0] = v;
    }
    __syncthreads();
    mx = red[0];

    float sum = 0.0f;
    #pragma unroll
    for (int i = 0; i < 8; i++) {
        vals[i] = __expf(vals[i] - mx);   // -inf -> exactly 0
        sum += vals[i];
    }
    __syncthreads();
    #pragma unroll
    for (int o = 16; o > 0; o >>= 1)
        sum += __shfl_xor_sync(0xFFFFFFFFu, sum, o);
    if ((tid & 31) == 0) red[tid >> 5] = sum;
    __syncthreads();
    if (tid == 0) {
        float v = red[0];
        #pragma unroll
        for (int w = 1; w < 8; w++) v += red[w];
        red[0] = v;
    }
    __syncthreads();
    const float inv = 1.0f / red[0];

    if (active) {
        f16 h[8];
        #pragma unroll
        for (int i = 0; i < 8; i++) h[i] = __float2half_rn(vals[i] * inv);
        *(uint4*)(Ph + ro + tid * 8) = *(uint4*)h;
    }
}

// ================= host launcher =================
extern "C" void kernel_launch(void* const* d_in, const int* in_sizes, int n_in,
                              void* d_out, int out_size)
{
    const float* query = (const float*)d_in[0];
    const float* kv    = (const float*)d_in[1];
    const void*  mask  = d_in[2];
    const float* Wq = (const float*)d_in[3];
    const float* bq = (const float*)d_in[4];
    const float* Wk = (const float*)d_in[5];
    const float* bk = (const float*)d_in[6];
    const float* Wv = (const float*)d_in[7];
    const float* bv = (const float*)d_in[8];
    const float* Wo = (const float*)d_in[9];
    const float* bo = (const float*)d_in[10];
    float* out = (float*)d_out;

    f16 *qc, *kvcomp, *WqT, *WkT, *WvT, *WoT;
    f16 *Qh, *Kh, *VT, *Sh, *Ph, *Ch;
    int *NV, *LK;
    cudaGetSymbolAddress((void**)&qc,  g_qc);
    cudaGetSymbolAddress((void**)&kvcomp, g_kvcomp);
    cudaGetSymbolAddress((void**)&WqT, g_WqT);  cudaGetSymbolAddress((void**)&WkT, g_WkT);
    cudaGetSymbolAddress((void**)&WvT, g_WvT);  cudaGetSymbolAddress((void**)&WoT, g_WoT);
    cudaGetSymbolAddress((void**)&Qh, g_Qh);    cudaGetSymbolAddress((void**)&Kh, g_Kh);
    cudaGetSymbolAddress((void**)&VT, g_VT);
    cudaGetSymbolAddress((void**)&Sh, g_Sh);    cudaGetSymbolAddress((void**)&Ph, g_Ph);
    cudaGetSymbolAddress((void**)&Ch, g_Ch);
    cudaGetSymbolAddress((void**)&NV, g_nvalid);
    cudaGetSymbolAddress((void**)&LK, g_lkvp);

    cudaFuncSetAttribute(mma_gemm<0,0>, cudaFuncAttributeMaxDynamicSharedMemorySize, DSMEM_B);
    cudaFuncSetAttribute(mma_gemm<0,1>, cudaFuncAttributeMaxDynamicSharedMemorySize, DSMEM_B);
    cudaFuncSetAttribute(mma_gemm<1,0>, cudaFuncAttributeMaxDynamicSharedMemorySize, DSMEM_B);
    cudaFuncSetAttribute(mma_gemm<2,2>, cudaFuncAttributeMaxDynamicSharedMemorySize, DSMEM_B);
    cudaFuncSetAttribute(mma_gemm<3,3>, cudaFuncAttributeMaxDynamicSharedMemorySize, DSMEM_B);
    cudaFuncSetAttribute(mma_gemm<5,2>, cudaFuncAttributeMaxDynamicSharedMemorySize, DSMEM_B);

    int nsm = 148;
    cudaDeviceGetAttribute(&nsm, cudaDevAttrMultiProcessorCount, 0);
    const int PGRID = nsm * 2;   // one balanced persistent wave (2 CTAs/SM)

    const float scale = 1.0f / 32.0f;  // 1/sqrt(1024)

    // 1. fused preprocess: compaction + 4x weight transpose + query convert
    {
        PPArgs pa;
        pa.query = query;
        pa.mask  = mask;
        pa.wsrc[0] = Wq;  pa.wdst[0] = WqT;
        pa.wsrc[1] = Wk;  pa.wdst[1] = WkT;
        pa.wsrc[2] = Wv;  pa.wdst[2] = WvT;
        pa.wsrc[3] = Wo;  pa.wdst[3] = WoT;
        preprocess_kernel<<<PP_TOTAL, 256>>>(pa);
    }

    // 2. gather compacted kv rows (fp16)
    gather_kv_kernel<<<dim3(LKV, BATCH), 128>>>(kv);

    // 3. Q projection -> Qh   (ncu control)
    mma_gemm<0,0><<<PGRID, 256, DSMEM_B>>>(
        qc, WqT, nullptr, Qh, bq, nullptr, nullptr, 0.0f,
        HID, QDIM, QDIM, QDIM, 0, 0, 0,
        HID / 128, (BATCH * LQ) / 128, 1);

    // 4. K projection on compacted rows -> Kh (dense M-limited tiles)
    mma_gemm<0,1><<<PGRID, 256, DSMEM_B>>>(
        kvcomp, WkT, nullptr, Kh, bk, NV, LK, 0.0f,
        HID, QDIM, QDIM, QDIM,
        (long long)LKV * QDIM, 0, (long long)LKV * HID,
        HID / 128, LKV / 128, BATCH);

    // 5. V projection directly transposed (dense N-limited tiles, row bias)
    mma_gemm<5,2><<<PGRID, 256, DSMEM_B>>>(
        WvT, kvcomp, nullptr, VT, bv, NV, LK, 0.0f,
        LKV, QDIM, QDIM, QDIM,
        0, (long long)LKV * QDIM, (long long)HID * LKV,
        LKV / 128, HID / 128, BATCH);

    // 6. scores (dense N-limited tiles): S = Q @ K^T -> f16
    mma_gemm<2,2><<<PGRID, 256, DSMEM_B>>>(
        Qh, Kh, nullptr, Sh, nullptr, NV, LK, scale,
        LKV, HID, HID, HID,
        (long long)LQ * HID, (long long)LKV * HID, (long long)LQ * LKV,
        LKV / 128, LQ / 128, BATCH);

    // 7. softmax over lkvp[b] -> Ph
    softmax_kernel<<<BATCH * LQ, 256>>>(Sh, Ph, LK);

    // 8. context (runtime K = lkvp[b]): C = P @ VT^T
    mma_gemm<3,3><<<PGRID, 256, DSMEM_B>>>(
        Ph, VT, nullptr, Ch, nullptr, NV, LK, 0.0f,
        HID, 0, LKV, LKV,
        (long long)LQ * LKV, (long long)HID * LKV, (long long)LQ * HID,
        HID / 128, LQ / 128, BATCH);

    // 9. output projection: out = C @ WoT^T + bo (fp32)
    mma_gemm<1,0><<<PGRID, 256, DSMEM_B>>>(
        Ch, WoT, out, nullptr, bo, nullptr, nullptr, 0.0f,
        QDIM, HID, HID, HID, 0, 0, 0,
        QDIM / 128, (BATCH * LQ) / 128, 1);
}

// round 16
// speedup vs baseline: 1.1601x; 1.0246x over previous
#include <cuda_runtime.h>
#include <cuda_fp16.h>
#include <stdint.h>

// Problem constants
#define BATCH 8
#define LQ    1024
#define LKV   2048
#define HID   1024
#define QDIM  1024

typedef __half f16;

// ================= scratch (static device globals) =================
__device__ __align__(16) f16 g_qc [(size_t)BATCH * LQ  * QDIM];   // query fp16
__device__ __align__(16) f16 g_kvcomp[(size_t)BATCH * LKV * QDIM]; // compacted kv fp16
__device__ __align__(16) f16 g_WqT[(size_t)HID * QDIM];
__device__ __align__(16) f16 g_WkT[(size_t)HID * QDIM];
__device__ __align__(16) f16 g_WvT[(size_t)HID * QDIM];
__device__ __align__(16) f16 g_WoT[(size_t)HID * QDIM];
__device__ __align__(16) f16  g_Qh [(size_t)BATCH * LQ  * HID];
__device__ __align__(16) f16  g_Kh [(size_t)BATCH * LKV * HID];   // compacted K
__device__ __align__(16) f16  g_VT [(size_t)BATCH * HID * LKV];   // compacted V^T
__device__ __align__(16) f16  g_Sh [(size_t)BATCH * LQ  * LKV];   // compacted scores (fp16)
__device__ __align__(16) f16  g_Ph [(size_t)BATCH * LQ  * LKV];   // compacted probs
__device__ __align__(16) f16  g_Ch [(size_t)BATCH * LQ  * HID];
__device__ int g_idx[(size_t)BATCH * LKV];   // compaction index
__device__ int g_nvalid[BATCH];
__device__ int g_lkvp[BATCH];                // nvalid rounded up to 128

// ================= PTX helpers =================
__device__ __forceinline__ uint32_t smem_to_u32(const void* p) {
    uint32_t a;
    asm("{ .reg .u64 t; cvta.to.shared.u64 t, %1; cvt.u32.u64 %0, t; }"
        : "=r"(a) : "l"(p));
    return a;
}

#define SWZ128(o) ((o) ^ (((o) >> 3) & 0x70))

__device__ __forceinline__ void cp16(uint32_t saddr, const void* g) {
    asm volatile("cp.async.cg.shared.global [%0], [%1], 16;"
                 :: "r"(saddr), "l"(g) : "memory");
}
#define CP_COMMIT() asm volatile("cp.async.commit_group;" ::: "memory")
#define CP_WAIT1()  asm volatile("cp.async.wait_group 1;" ::: "memory")
#define CP_WAIT0()  asm volatile("cp.async.wait_group 0;" ::: "memory")

__device__ __forceinline__ void ldsm4(uint32_t* r, uint32_t addr) {
    asm volatile("ldmatrix.sync.aligned.m8n8.x4.shared.b16 {%0,%1,%2,%3}, [%4];"
                 : "=r"(r[0]), "=r"(r[1]), "=r"(r[2]), "=r"(r[3]) : "r"(addr));
}

__device__ __forceinline__ void mma16816(float* d, const uint32_t* a,
                                         uint32_t b0, uint32_t b1) {
    asm volatile(
        "mma.sync.aligned.m16n8k16.row.col.f32.f16.f16.f32 "
        "{%0,%1,%2,%3}, {%4,%5,%6,%7}, {%8,%9}, {%0,%1,%2,%3};"
        : "+f"(d[0]), "+f"(d[1]), "+f"(d[2]), "+f"(d[3])
        : "r"(a[0]), "r"(a[1]), "r"(a[2]), "r"(a[3]), "r"(b0), "r"(b1));
}

// ================= fused preprocess kernel =================
#define PP_COMPACT 8
#define PP_WT_PER  256
#define PP_WT      (4 * PP_WT_PER)
#define PP_CONV    ((BATCH * LQ * QDIM / 4) / 256)   // 8192
#define PP_TOTAL   (PP_COMPACT + PP_WT + PP_CONV)

struct PPArgs {
    const float* query;
    const void*  mask;
    const float* wsrc[4];
    f16*         wdst[4];
};

__global__ void __launch_bounds__(256)
preprocess_kernel(PPArgs args)
{
    const int bid = blockIdx.x;
    const int tid = threadIdx.x;

    if (bid < PP_COMPACT) {
        const int b = bid;
        const void* mask_raw = args.mask;

        __shared__ int s_bad;
        if (tid == 0) s_bad = 0;
        __syncthreads();
        {
            const int* w = (const int*)mask_raw;
            int bad = 0;
            for (int i = tid; i < 4096; i += 256)
                if ((unsigned)w[i] > 1u) bad = 1;
            if (bad) atomicOr(&s_bad, 1);
        }
        __syncthreads();
        const int is_u8 = s_bad;

        const int base = tid * 8;
        int m[8], cnt = 0;
        #pragma unroll
        for (int i = 0; i < 8; i++) {
            const int gi = b * LKV + base + i;
            int v = is_u8 ? (((const uint8_t*)mask_raw)[gi] != 0)
                          : (((const int*)mask_raw)[gi] != 0);
            m[i] = v;
            cnt += v;
        }

        const int lane = tid & 31, w = tid >> 5;
        int v = cnt;
        #pragma unroll
        for (int o = 1; o < 32; o <<= 1) {
            int t = __shfl_up_sync(0xFFFFFFFFu, v, o);
            if (lane >= o) v += t;
        }
        __shared__ int ws[8];
        if (lane == 31) ws[w] = v;
        __syncthreads();
        __shared__ int total;
        if (tid == 0) {
            int s = 0;
            #pragma unroll
            for (int i = 0; i < 8; i++) { int t = ws[i]; ws[i] = s; s += t; }
            total = s;
        }
        __syncthreads();
        int pos = v - cnt + ws[w];

        #pragma unroll
        for (int i = 0; i < 8; i++)
            if (m[i]) g_idx[b * LKV + pos++] = base + i;

        if (tid == 0) {
            g_nvalid[b] = total;
            g_lkvp[b]   = (total + 127) & ~127;
        }
    } else if (bid < PP_COMPACT + PP_WT) {
        const int t2 = bid - PP_COMPACT;
        const int z  = t2 / PP_WT_PER;
        const int ti = t2 - z * PP_WT_PER;
        const int br = (ti & 7) * 128;
        const int bc = (ti >> 3) * 32;
        const float* x = args.wsrc[z];
        f16*        th = args.wdst[z];

        __shared__ float t[32][129];

        #pragma unroll
        for (int p = 0; p < 4; p++) {
            const int r  = p * 32 + (tid >> 3);
            const int c4 = (tid & 7) * 4;
            float4 vv = *(const float4*)(x + (long long)(br + r) * 1024 + bc + c4);
            t[c4 + 0][r] = vv.x;
            t[c4 + 1][r] = vv.y;
            t[c4 + 2][r] = vv.z;
            t[c4 + 3][r] = vv.w;
        }
        __syncthreads();

        const int c  = tid >> 3;
        const int r0 = (tid & 7) * 16;
        f16 h[16];
        #pragma unroll
        for (int i = 0; i < 16; i++) h[i] = __float2half_rn(t[c][r0 + i]);
        f16* op = th + (long long)(bc + c) * 1024 + br + r0;
        *(uint4*)(op)     = *(uint4*)(h);
        *(uint4*)(op + 8) = *(uint4*)(h + 8);
    } else {
        const long long i = (long long)(bid - PP_COMPACT - PP_WT) * 256 + tid;
        float4 v = *(const float4*)(args.query + i * 4);
        f16 hh[4] = {__float2half_rn(v.x), __float2half_rn(v.y),
                     __float2half_rn(v.z), __float2half_rn(v.w)};
        f16* qc = g_qc;
        *(uint2*)(qc + i * 4) = *(uint2*)hh;
    }
}

// Gather + fp32->fp16 convert
__global__ void __launch_bounds__(128)
gather_kv_kernel(const float* __restrict__ kv)
{
    const int j = blockIdx.x, b = blockIdx.y, t = threadIdx.x;
    if (j >= g_lkvp[b]) return;
    f16* dst = g_kvcomp + ((size_t)b * LKV + j) * QDIM;
    if (j < g_nvalid[b]) {
        const float* src = kv + ((size_t)b * LKV + g_idx[b * LKV + j]) * QDIM;
        float4 a = *(const float4*)(src + t * 8);
        float4 c = *(const float4*)(src + t * 8 + 4);
        f16 h[8] = {__float2half_rn(a.x), __float2half_rn(a.y),
                    __float2half_rn(a.z), __float2half_rn(a.w),
                    __float2half_rn(c.x), __float2half_rn(c.y),
                    __float2half_rn(c.z), __float2half_rn(c.w)};
        *(uint4*)(dst + t * 8) = *(uint4*)h;
    } else {
        *(uint4*)(dst + t * 8) = make_uint4(0, 0, 0, 0);
    }
}

// ================= GEMM tile body (shared by both GEMM kernels) =================
#define BKT 64
#define STAGE_B 32768
#define NSTAGE 3
#define DSMEM_B (NSTAGE * STAGE_B)   // 96KB

// Runs the full K-loop for one 128x128 tile; acc[2][8][4] output.
__device__ __forceinline__ void gemm_tile(
    uint32_t sbase, int tid, int wm, int wn, int lane,
    const f16* baseA, const f16* baseB, int ldA, int ldB, int Kd,
    float acc[2][8][4])
{
    #pragma unroll
    for (int mi = 0; mi < 2; mi++)
        #pragma unroll
        for (int nj = 0; nj < 8; nj++)
            #pragma unroll
            for (int q = 0; q < 4; q++) acc[mi][nj][q] = 0.0f;

    const int KT = Kd / BKT;

    auto load_stage = [&](int kt, int s) {
        const int k0 = kt * BKT;
        #pragma unroll
        for (int sub = 0; sub < 2; sub++) {
            const f16* gb = sub ? baseB : baseA;
            const int ld  = sub ? ldB : ldA;
            const uint32_t so = sbase + s * STAGE_B + sub * 16384;
            #pragma unroll
            for (int i = 0; i < 4; i++) {
                const int c  = i * 256 + tid;
                const int r  = c >> 3;
                const int kc = c & 7;
                cp16(so + SWZ128((uint32_t)(r * 128 + kc * 16)),
                     gb + (long long)r * ld + k0 + kc * 8);
            }
        }
        CP_COMMIT();
    };

    load_stage(0, 0);
    if (KT > 1) load_stage(1, 1);

    for (int kt = 0; kt < KT; kt++) {
        const int s = kt % NSTAGE;
        if (kt + 1 < KT) CP_WAIT1(); else CP_WAIT0();
        __syncthreads();
        if (kt + 2 < KT) load_stage(kt + 2, (kt + 2) % NSTAGE);

        const uint32_t aS = sbase + s * STAGE_B;
        const uint32_t bS = aS + 16384;

        #pragma unroll
        for (int ks = 0; ks < 4; ks++) {
            const int chunk = ks * 32 + (lane >> 4) * 16;
            uint32_t af[2][4];
            #pragma unroll
            for (int mi = 0; mi < 2; mi++) {
                const int r = wm * 32 + mi * 16 + (lane & 15);
                ldsm4(af[mi], aS + SWZ128((uint32_t)(r * 128 + chunk)));
            }
            uint32_t bf[4][4];
            #pragma unroll
            for (int ni = 0; ni < 4; ni++) {
                const int r = wn * 64 + ni * 16 + (lane & 15);
                ldsm4(bf[ni], bS + SWZ128((uint32_t)(r * 128 + chunk)));
            }
            #pragma unroll
            for (int mi = 0; mi < 2; mi++) {
                #pragma unroll
                for (int nj = 0; nj < 8; nj++) {
                    const int ni = nj >> 1, oct = nj & 1;
                    mma16816(acc[mi][nj], af[mi], bf[ni][oct], bf[ni][oct + 2]);
                }
            }
        }
    }
}

// ============ fused Q/K/V projection (one persistent launch) ============
// Problem 0: Qh[8192,1024]  = qc @ WqT^T + bq[col]        (512 tiles)
// Problem 1: Kh[b][lkvp,1024] = kvcomp[b] @ WkT^T + bk[col] (dense per batch)
// Problem 2: VT[b][1024,lkvp] = WvT @ kvcomp[b]^T + bv[row] (dense per batch)
// All: Kd=1024, ldA=ldB=1024.
__global__ void __launch_bounds__(256, 2)
mma_qkv(const f16* __restrict__ qc, const f16* __restrict__ kvcomp,
        const f16* __restrict__ WqT, const f16* __restrict__ WkT,
        const f16* __restrict__ WvT,
        f16* __restrict__ Qh, f16* __restrict__ Kh, f16* __restrict__ VT,
        const float* __restrict__ bq, const float* __restrict__ bk,
        const float* __restrict__ bv,
        const int* __restrict__ d_lkvp)
{
    extern __shared__ char smem[];
    const uint32_t sbase = smem_to_u32(smem);

    const int tid  = threadIdx.x;
    const int wid = tid >> 5, lane = tid & 31;
    const int wm = wid & 3;
    const int wn = wid >> 2;

    // dense cumulative tile counts per batch (same count for K and V problems)
    int cum[BATCH + 1];
    {
        int s = 0;
        #pragma unroll
        for (int b2 = 0; b2 < BATCH; b2++) {
            cum[b2] = s;
            s += (d_lkvp[b2] >> 7) * 8;    // (lkvp/128) tiles x 8 (HID/128)
        }
        cum[BATCH] = s;
    }
    const int nQ = (BATCH * LQ / 128) * (HID / 128);   // 512
    const int per = cum[BATCH];
    const int ntiles = nQ + 2 * per;

    for (int t = blockIdx.x; t < ntiles; t += gridDim.x) {
        const f16 *baseA, *baseB;
        f16* O;
        const float* bias;
        int rowBias = 0;
        long long No;
        int tileM, tileN;

        if (t < nQ) {
            const int ty = t >> 3, tx = t & 7;
            tileM = ty * 128; tileN = tx * 128;
            baseA = qc  + (long long)tileM * QDIM;
            baseB = WqT + (long long)tileN * QDIM;
            O = Qh; bias = bq; No = HID;
        } else {
            int u = t - nQ;
            const int pk = (u >= per) ? 1 : 0;
            if (pk) u -= per;
            int b = 0;
            while (u >= cum[b + 1]) b++;
            const int local = u - cum[b];
            const int nt = d_lkvp[b] >> 7;
            if (pk == 0) {
                // K projection: M tiles over nt, N tiles over 8
                const int ty = local >> 3, tx = local & 7;
                tileM = ty * 128; tileN = tx * 128;
                baseA = kvcomp + (long long)b * LKV * QDIM + (long long)tileM * QDIM;
                baseB = WkT + (long long)tileN * QDIM;
                O = Kh + (long long)b * LKV * HID;
                bias = bk; No = HID;
            } else {
                // V projection (transposed): M tiles over 8, N tiles over nt
                const int ty = local / nt, tx = local - ty * nt;
                tileM = ty * 128; tileN = tx * 128;
                baseA = WvT + (long long)tileM * QDIM;
                baseB = kvcomp + (long long)b * LKV * QDIM + (long long)tileN * QDIM;
                O = VT + (long long)b * HID * LKV;
                bias = bv; No = LKV; rowBias = 1;
            }
        }

        float acc[2][8][4];
        gemm_tile(sbase, tid, wm, wn, lane, baseA, baseB, QDIM, QDIM, QDIM, acc);

        #pragma unroll
        for (int mi = 0; mi < 2; mi++) {
            #pragma unroll
            for (int nj = 0; nj < 8; nj++) {
                const int row = tileM + wm * 32 + mi * 16 + (lane >> 2);
                const int col = tileN + wn * 64 + nj * 8 + (lane & 3) * 2;
                #pragma unroll
                for (int half = 0; half < 2; half++) {
                    const int r = row + half * 8;
                    float v0 = acc[mi][nj][half * 2];
                    float v1 = acc[mi][nj][half * 2 + 1];
                    if (rowBias) {
                        const float bvv = __ldg(bias + r);
                        v0 += bvv;
                        v1 += bvv;
                    } else {
                        v0 += __ldg(bias + col);
                        v1 += __ldg(bias + col + 1);
                    }
                    f16 h2[2] = {__float2half_rn(v0), __float2half_rn(v1)};
                    *(uint32_t*)(O + (long long)r * No + col) = *(uint32_t*)h2;
                }
            }
        }
        __syncthreads();
    }
}

// ================= persistent GEMM (scores / context / O-proj) =================
// EPI: 1=+bias[col]->fp32 ; 2=compact mask*scale->f16 ; 3=plain->f16
// VAR: 0=none ; 2=N limited (dense; EPI2 masks by nvalid) ; 3=K runtime=lkvp[b]
template <int EPI, int VAR>
__global__ void __launch_bounds__(256, 2)
mma_gemm(const f16* __restrict__ A, const f16* __restrict__ B,
         float* __restrict__ Cf, f16* __restrict__ Oh,
         const float* __restrict__ bias,
         const int* __restrict__ d_nv, const int* __restrict__ d_lkvp,
         float scale, int N, int KdHost, int ldA, int ldB,
         long long sA, long long sB, long long sC,
         int gx, int gy, int gz)
{
    extern __shared__ char smem[];
    const uint32_t sbase = smem_to_u32(smem);

    const int tid  = threadIdx.x;
    const int wid = tid >> 5, lane = tid & 31;
    const int wm = wid & 3;
    const int wn = wid >> 2;

    int cum[BATCH + 1];
    int ntiles;
    if (VAR == 2) {
        int s = 0;
        for (int b2 = 0; b2 < gz; b2++) {
            cum[b2] = s;
            s += gy * (d_lkvp[b2] >> 7);
        }
        cum[gz] = s;
        ntiles = s;
    } else {
        ntiles = gx * gy * gz;
    }

    for (int t = blockIdx.x; t < ntiles; t += gridDim.x) {
        int b, ty, tx;
        if (VAR == 2) {
            b = 0;
            while (t >= cum[b + 1]) b++;
            const int local = t - cum[b];
            const int nt = d_lkvp[b] >> 7;
            ty = local / nt;
            tx = local - ty * nt;
        } else {
            b = t / (gx * gy);
            const int r2 = t - b * (gx * gy);
            ty = r2 / gx;
            tx = r2 - ty * gx;
        }
        const int tileM = ty * 128;
        const int tileN = tx * 128;
        const int Kd = (VAR == 3) ? d_lkvp[b] : KdHost;

        const f16* baseA = A + (long long)b * sA + (long long)tileM * ldA;
        const f16* baseB = B + (long long)b * sB + (long long)tileN * ldB;

        float acc[2][8][4];
        gemm_tile(sbase, tid, wm, wn, lane, baseA, baseB, ldA, ldB, Kd, acc);

        float* cf = Cf ? Cf + (long long)b * sC : nullptr;
        f16*   oh = Oh ? Oh + (long long)b * sC : nullptr;
        const int nv = (VAR == 2 && EPI == 2) ? d_nv[b] : 0;

        #pragma unroll
        for (int mi = 0; mi < 2; mi++) {
            #pragma unroll
            for (int nj = 0; nj < 8; nj++) {
                const int row = tileM + wm * 32 + mi * 16 + (lane >> 2);
                const int col = tileN + wn * 64 + nj * 8 + (lane & 3) * 2;
                #pragma unroll
                for (int half = 0; half < 2; half++) {
                    const int r = row + half * 8;
                    float v0 = acc[mi][nj][half * 2];
                    float v1 = acc[mi][nj][half * 2 + 1];
                    if (EPI == 1) {
                        v0 += __ldg(bias + col);
                        v1 += __ldg(bias + col + 1);
                    } else if (EPI == 2) {
                        v0 = (col     < nv) ? v0 * scale : -1e9f;
                        v1 = (col + 1 < nv) ? v1 * scale : -1e9f;
                    }
                    if (EPI == 1) {
                        *(float2*)(cf + (long long)r * N + col) = make_float2(v0, v1);
                    } else {
                        f16 h2[2] = {__float2half_rn(v0), __float2half_rn(v1)};
                        *(uint32_t*)(oh + (long long)r * N + col) = *(uint32_t*)h2;
                    }
                }
            }
        }
        __syncthreads();
    }
}

// ============ softmax over compacted row length lkvp[b], fp16 in/out ============
__global__ void __launch_bounds__(256)
softmax_kernel(const f16* __restrict__ S, f16* __restrict__ Ph,
               const int* __restrict__ d_lkvp)
{
    const int b = blockIdx.x >> 10;
    const int len = d_lkvp[b];
    const long long ro = (long long)blockIdx.x * LKV;
    const int tid = threadIdx.x;
    const bool active = (tid * 8) < len;

    float vals[8];
    if (active) {
        uint4 pk = *(const uint4*)(S + ro + tid * 8);
        const f16* hp = (const f16*)&pk;
        #pragma unroll
        for (int i = 0; i < 8; i++) vals[i] = __half2float(hp[i]);
    } else {
        #pragma unroll
        for (int i = 0; i < 8; i++) vals[i] = -1e30f;
    }

    float mx = vals[0];
    #pragma unroll
    for (int i = 1; i < 8; i++) mx = fmaxf(mx, vals[i]);

    __shared__ float red[8];
    #pragma unroll
    for (int o = 16; o > 0; o >>= 1)
        mx = fmaxf(mx, __shfl_xor_sync(0xFFFFFFFFu, mx, o));
    if ((tid & 31) == 0) red[tid >> 5] = mx;
    __syncthreads();
    if (tid == 0) {
        float v = red[0];
        #pragma unroll
        for (int w = 1; w < 8; w++) v = fmaxf(v, red[w]);
        red[0] = v;
    }
    __syncthreads();
    mx = red[0];

    float sum = 0.0f;
    #pragma unroll
    for (int i = 0; i < 8; i++) {
        vals[i] = __expf(vals[i] - mx);
        sum += vals[i];
    }
    __syncthreads();
    #pragma unroll
    for (int o = 16; o > 0; o >>= 1)
        sum += __shfl_xor_sync(0xFFFFFFFFu, sum, o);
    if ((tid & 31) == 0) red[tid >> 5] = sum;
    __syncthreads();
    if (tid == 0) {
        float v = red[0];
        #pragma unroll
        for (int w = 1; w < 8; w++) v += red[w];
        red[0] = v;
    }
    __syncthreads();
    const float inv = 1.0f / red[0];

    if (active) {
        f16 h[8];
        #pragma unroll
        for (int i = 0; i < 8; i++) h[i] = __float2half_rn(vals[i] * inv);
        *(uint4*)(Ph + ro + tid * 8) = *(uint4*)h;
    }
}

// ================= host launcher =================
extern "C" void kernel_launch(void* const* d_in, const int* in_sizes, int n_in,
                              void* d_out, int out_size)
{
    const float* query = (const float*)d_in[0];
    const float* kv    = (const float*)d_in[1];
    const void*  mask  = d_in[2];
    const float* Wq = (const float*)d_in[3];
    const float* bq = (const float*)d_in[4];
    const float* Wk = (const float*)d_in[5];
    const float* bk = (const float*)d_in[6];
    const float* Wv = (const float*)d_in[7];
    const float* bv = (const float*)d_in[8];
    const float* Wo = (const float*)d_in[9];
    const float* bo = (const float*)d_in[10];
    float* out = (float*)d_out;

    f16 *qc, *kvcomp, *WqT, *WkT, *WvT, *WoT;
    f16 *Qh, *Kh, *VT, *Sh, *Ph, *Ch;
    int *NV, *LK;
    cudaGetSymbolAddress((void**)&qc,  g_qc);
    cudaGetSymbolAddress((void**)&kvcomp, g_kvcomp);
    cudaGetSymbolAddress((void**)&WqT, g_WqT);  cudaGetSymbolAddress((void**)&WkT, g_WkT);
    cudaGetSymbolAddress((void**)&WvT, g_WvT);  cudaGetSymbolAddress((void**)&WoT, g_WoT);
    cudaGetSymbolAddress((void**)&Qh, g_Qh);    cudaGetSymbolAddress((void**)&Kh, g_Kh);
    cudaGetSymbolAddress((void**)&VT, g_VT);
    cudaGetSymbolAddress((void**)&Sh, g_Sh);    cudaGetSymbolAddress((void**)&Ph, g_Ph);
    cudaGetSymbolAddress((void**)&Ch, g_Ch);
    cudaGetSymbolAddress((void**)&NV, g_nvalid);
    cudaGetSymbolAddress((void**)&LK, g_lkvp);

    cudaFuncSetAttribute(mma_qkv,      cudaFuncAttributeMaxDynamicSharedMemorySize, DSMEM_B);
    cudaFuncSetAttribute(mma_gemm<1,0>, cudaFuncAttributeMaxDynamicSharedMemorySize, DSMEM_B);
    cudaFuncSetAttribute(mma_gemm<2,2>, cudaFuncAttributeMaxDynamicSharedMemorySize, DSMEM_B);
    cudaFuncSetAttribute(mma_gemm<3,3>, cudaFuncAttributeMaxDynamicSharedMemorySize, DSMEM_B);

    int nsm = 148;
    cudaDeviceGetAttribute(&nsm, cudaDevAttrMultiProcessorCount, 0);
    const int PGRID = nsm * 2;   // one balanced persistent wave (2 CTAs/SM)

    const float scale = 1.0f / 32.0f;  // 1/sqrt(1024)

    // 1. fused preprocess: compaction + 4x weight transpose + query convert
    {
        PPArgs pa;
        pa.query = query;
        pa.mask  = mask;
        pa.wsrc[0] = Wq;  pa.wdst[0] = WqT;
        pa.wsrc[1] = Wk;  pa.wdst[1] = WkT;
        pa.wsrc[2] = Wv;  pa.wdst[2] = WvT;
        pa.wsrc[3] = Wo;  pa.wdst[3] = WoT;
        preprocess_kernel<<<PP_TOTAL, 256>>>(pa);
    }

    // 2. gather compacted kv rows (fp16)
    gather_kv_kernel<<<dim3(LKV, BATCH), 128>>>(kv);

    // 3. fused Q + K + V projections (single persistent launch)
    mma_qkv<<<PGRID, 256, DSMEM_B>>>(
        qc, kvcomp, WqT, WkT, WvT, Qh, Kh, VT, bq, bk, bv, LK);

    // 4. scores (dense N-limited tiles): S = Q @ K^T -> f16
    mma_gemm<2,2><<<PGRID, 256, DSMEM_B>>>(
        Qh, Kh, nullptr, Sh, nullptr, NV, LK, scale,
        LKV, HID, HID, HID,
        (long long)LQ * HID, (long long)LKV * HID, (long long)LQ * LKV,
        LKV / 128, LQ / 128, BATCH);

    // 5. softmax over lkvp[b] -> Ph
    softmax_kernel<<<BATCH * LQ, 256>>>(Sh, Ph, LK);

    // 6. context (runtime K = lkvp[b]): C = P @ VT^T
    mma_gemm<3,3><<<PGRID, 256, DSMEM_B>>>(
        Ph, VT, nullptr, Ch, nullptr, NV, LK, 0.0f,
        HID, 0, LKV, LKV,
        (long long)LQ * LKV, (long long)HID * LKV, (long long)LQ * HID,
        HID / 128, LQ / 128, BATCH);

    // 7. output projection: out = C @ WoT^T + bo (fp32)
    mma_gemm<1,0><<<PGRID, 256, DSMEM_B>>>(
        Ch, WoT, out, nullptr, bo, nullptr, nullptr, 0.0f,
        QDIM, HID, HID, HID, 0, 0, 0,
        QDIM / 128, (BATCH * LQ) / 128, 1);
}